// round 2
// baseline (speedup 1.0000x reference)
#include <cuda_runtime.h>
#include <cuda_bf16.h>

#define R_TOTAL 65536   // T*B = 2048*32
#define XDIM    1024

// ---- scratch (static device arrays; no allocation) ----
__device__ float g_h2[(size_t)R_TOTAL * 128];   // [row][mlp(2)][64]   32 MB
__device__ float g_part[4][R_TOTAL];            // per-colblock partial row sums

// ln(d!) for d = 0..9 (data values are integers 0..9)
__constant__ float c_LGF[10] = {
    0.0f, 0.0f, 0.6931471805599453f, 1.791759469228055f, 3.1780538303479458f,
    4.787491742782046f, 6.579251212010101f, 8.525161361065415f,
    10.604602902745251f, 12.801827480081469f
};

__device__ __forceinline__ float ex2f(float x){ float r; asm("ex2.approx.f32 %0, %1;" : "=f"(r) : "f"(x)); return r; }
__device__ __forceinline__ float lg2f(float x){ float r; asm("lg2.approx.f32 %0, %1;" : "=f"(r) : "f"(x)); return r; }

__device__ __forceinline__ float tanh_fast(float x){
    float xc = fminf(fmaxf(x, -9.0f), 9.0f);
    float e  = ex2f(xc * 2.885390081777927f);   // e^{2x} = 2^{2x*log2e}
    return __fdividef(e - 1.0f, e + 1.0f);
}

// log2(1 + e^y), numerically stable
__device__ __forceinline__ float softplus_log2(float y){
    float t = y * 1.4426950408889634f;
    return fmaxf(t, 0.0f) + lg2f(1.0f + ex2f(-fabsf(t)));
}

// ===========================================================================
// K1: layers 1+2 for both MLPs. 64 rows per block, 256 threads.
// smem: xsh[64*32] | h1sh[2*64*257] (padded) | w2sh[2*64*64] (K-chunk)
// ===========================================================================
#define K1_XSH   0
#define K1_H1SH  (64*32)
#define K1_W2SH  (K1_H1SH + 2*64*257)
#define K1_SMEM_FLOATS (K1_W2SH + 2*64*64)

__global__ void __launch_bounds__(256, 1) k1_mlp12(
    const float* __restrict__ w,
    const float* __restrict__ W1r, const float* __restrict__ b1r,
    const float* __restrict__ W2r, const float* __restrict__ b2r,
    const float* __restrict__ W1v, const float* __restrict__ b1v,
    const float* __restrict__ W2v, const float* __restrict__ b2v)
{
    extern __shared__ float sm[];
    float* xsh  = sm + K1_XSH;
    float* h1sh = sm + K1_H1SH;
    float* w2sh = sm + K1_W2SH;

    const int tid  = threadIdx.x;
    const int row0 = blockIdx.x * 64;

    // stage w[row0 .. row0+64)[32]
    {
        const float4* src = (const float4*)(w + (size_t)row0 * 32);
        float4* dst = (float4*)xsh;
        for (int i = tid; i < 64*32/4; i += 256) dst[i] = src[i];
    }

    // ---- layer 1: thread owns output col c for both MLPs ----
    const int c = tid;
    float w1a[16], w1b[16];
    #pragma unroll
    for (int k = 0; k < 16; k++){ w1a[k] = W1r[k*256 + c]; w1b[k] = W1v[k*256 + c]; }
    const float ba = b1r[c], bb = b1v[c];
    __syncthreads();

    #pragma unroll 4
    for (int r = 0; r < 64; r++){
        float xr[32];
        #pragma unroll
        for (int q = 0; q < 8; q++) *(float4*)&xr[q*4] = *(float4*)&xsh[r*32 + q*4];
        float a0 = ba, a1 = bb;
        // rate inputs: channels 0..7 and 16..23; v inputs: 8..15 and 24..31
        #pragma unroll
        for (int k = 0; k < 8; k++){
            a0 = fmaf(xr[k],      w1a[k],     a0);
            a0 = fmaf(xr[k + 16], w1a[k + 8], a0);
            a1 = fmaf(xr[k + 8],  w1b[k],     a1);
            a1 = fmaf(xr[k + 24], w1b[k + 8], a1);
        }
        h1sh[(0*64 + r)*257 + c] = tanh_fast(a0);
        h1sh[(1*64 + r)*257 + c] = tanh_fast(a1);
    }

    // ---- layer 2: thread tile = 4 rows x 4 cols x 2 mlps ----
    const int ci = tid & 15, rg = tid >> 4;
    const int c0 = ci * 4,  r0 = rg * 4;

    float acc[2][4][4];
    {
        float4 br = *(const float4*)&b2r[c0];
        float4 bv = *(const float4*)&b2v[c0];
        #pragma unroll
        for (int rr = 0; rr < 4; rr++){
            acc[0][rr][0]=br.x; acc[0][rr][1]=br.y; acc[0][rr][2]=br.z; acc[0][rr][3]=br.w;
            acc[1][rr][0]=bv.x; acc[1][rr][1]=bv.y; acc[1][rr][2]=bv.z; acc[1][rr][3]=bv.w;
        }
    }

    for (int kc = 0; kc < 4; kc++){          // K = 256 in chunks of 64
        __syncthreads();
        for (int q = tid; q < 2048; q += 256){   // stage W2 chunk [2][64][64] (float4 units)
            int m   = q >> 10;
            int rem = q & 1023;
            int kk  = rem >> 4;
            int cq  = rem & 15;
            const float* W2m = m ? W2v : W2r;
            *(float4*)&w2sh[(m*64 + kk)*64 + cq*4] =
                *(const float4*)&W2m[(kc*64 + kk)*64 + cq*4];
        }
        __syncthreads();
        #pragma unroll 8
        for (int kk = 0; kk < 64; kk++){
            const int k = kc*64 + kk;
            float4 wr = *(float4*)&w2sh[(0*64 + kk)*64 + c0];
            float4 wv = *(float4*)&w2sh[(1*64 + kk)*64 + c0];
            #pragma unroll
            for (int rr = 0; rr < 4; rr++){
                float h0 = h1sh[(0*64 + r0 + rr)*257 + k];
                float h1 = h1sh[(1*64 + r0 + rr)*257 + k];
                acc[0][rr][0] = fmaf(h0, wr.x, acc[0][rr][0]);
                acc[0][rr][1] = fmaf(h0, wr.y, acc[0][rr][1]);
                acc[0][rr][2] = fmaf(h0, wr.z, acc[0][rr][2]);
                acc[0][rr][3] = fmaf(h0, wr.w, acc[0][rr][3]);
                acc[1][rr][0] = fmaf(h1, wv.x, acc[1][rr][0]);
                acc[1][rr][1] = fmaf(h1, wv.y, acc[1][rr][1]);
                acc[1][rr][2] = fmaf(h1, wv.z, acc[1][rr][2]);
                acc[1][rr][3] = fmaf(h1, wv.w, acc[1][rr][3]);
            }
        }
    }

    // tanh + store h2: layout g_h2[row][m][64]
    #pragma unroll
    for (int m = 0; m < 2; m++){
        #pragma unroll
        for (int rr = 0; rr < 4; rr++){
            float4 o;
            o.x = tanh_fast(acc[m][rr][0]);
            o.y = tanh_fast(acc[m][rr][1]);
            o.z = tanh_fast(acc[m][rr][2]);
            o.w = tanh_fast(acc[m][rr][3]);
            *(float4*)&g_h2[((size_t)(row0 + r0 + rr)*2 + m)*64 + c0] = o;
        }
    }
}

// ===========================================================================
// K2: layer 3 + decode + Z + logpmf + partial reduction.
// Block = 32 rows x 256 cols (grid.y = colblock). 256 threads.
// Thread: row r = tid>>3, lane8 = tid&7; owns cols lane8*4 + i*32, i=0..7
// smem: h2sh[32][2][65] padded | w3sh[2][64][256]
// ===========================================================================
#define K2_H2SH  0
#define K2_W3SH  (32*2*65)
#define K2_SMEM_FLOATS (K2_W3SH + 2*64*256)

__global__ void __launch_bounds__(256, 1) k2_layer3(
    const float* __restrict__ data,
    const float* __restrict__ W3r, const float* __restrict__ b3r,
    const float* __restrict__ W3v, const float* __restrict__ b3v)
{
    extern __shared__ float sm[];
    float* h2sh = sm + K2_H2SH;
    float* w3sh = sm + K2_W3SH;

    const int tid   = threadIdx.x;
    const int row0  = blockIdx.x * 32;
    const int cb    = blockIdx.y;          // colblock 0..3 (256 cols each)
    const int r     = tid >> 3;
    const int lane8 = tid & 7;

    // stage h2 for 32 rows (4096 floats), padded layout (r*2+m)*65 + k
    for (int q = tid; q < 4096; q += 256){
        int rr  = q >> 7;
        int rem = q & 127;            // m*64 + k
        int m   = rem >> 6;
        int k   = rem & 63;
        h2sh[(rr*2 + m)*65 + k] = g_h2[(size_t)(row0 + rr)*128 + rem];
    }
    // stage W3 col-tile [2][64][256] (8192 float4 / 4 = ... 8192 floats*4) -> 8192 float4? no: 32768 floats = 8192 float4
    {
        float4* dst = (float4*)w3sh;
        const float4* s0 = (const float4*)W3r;
        const float4* s1 = (const float4*)W3v;
        for (int q = tid; q < 8192; q += 256){
            int m  = q >> 12;          // 4096 float4 per mlp
            int kk = (q >> 6) & 63;
            int cf = q & 63;
            dst[q] = (m ? s1 : s0)[kk*256 + cb*64 + cf];
        }
    }
    __syncthreads();

    // accumulators init with bias
    float4 acc[2][8];
    {
        const float4* br4 = (const float4*)b3r;
        const float4* bv4 = (const float4*)b3v;
        #pragma unroll
        for (int i = 0; i < 8; i++){
            acc[0][i] = br4[cb*64 + lane8 + i*8];
            acc[1][i] = bv4[cb*64 + lane8 + i*8];
        }
    }

    // GEMM: K = 64
    const float4* w3f4 = (const float4*)w3sh;
    const float*  h2r  = &h2sh[(r*2)*65];
    #pragma unroll 4
    for (int k = 0; k < 64; k++){
        float h0 = h2r[k];
        float h1 = h2r[65 + k];
        #pragma unroll
        for (int i = 0; i < 8; i++){
            float4 wr = w3f4[k*64 + lane8 + i*8];
            float4 wv = w3f4[(64 + k)*64 + lane8 + i*8];
            acc[0][i].x = fmaf(h0, wr.x, acc[0][i].x);
            acc[0][i].y = fmaf(h0, wr.y, acc[0][i].y);
            acc[0][i].z = fmaf(h0, wr.z, acc[0][i].z);
            acc[0][i].w = fmaf(h0, wr.w, acc[0][i].w);
            acc[1][i].x = fmaf(h1, wv.x, acc[1][i].x);
            acc[1][i].y = fmaf(h1, wv.y, acc[1][i].y);
            acc[1][i].z = fmaf(h1, wv.z, acc[1][i].z);
            acc[1][i].w = fmaf(h1, wv.w, acc[1][i].w);
        }
    }

    // ---- fused elementwise + per-thread reduction ----
    // log2((j)!), j = 0..19
    const float LG2F[20] = {
        0.0f, 0.0f, 1.0f, 2.584962500721156f, 4.584962500721156f,
        6.906890595608519f, 9.491853096329675f, 12.299208018387276f,
        15.299208018387276f, 18.469133208679456f, 21.791061114716956f,
        25.250492704179430f, 28.835455204900587f, 32.535894893085060f,
        36.343249797356830f, 40.250140418953415f, 44.250140418953415f,
        48.337603188711560f, 52.507528197247871f, 56.755455722893512f
    };
    const int   rowg = row0 + r;
    const float LN2  = 0.6931471805599453f;
    float s = 0.0f;

    #pragma unroll 2
    for (int i = 0; i < 8; i++){
        float4 d4 = *(const float4*)&data[(size_t)rowg*1024 + cb*256 + lane8*4 + i*32];
        float dv[4] = {d4.x, d4.y, d4.z, d4.w};
        float ya[4] = {acc[0][i].x, acc[0][i].y, acc[0][i].z, acc[0][i].w};
        float yb[4] = {acc[1][i].x, acc[1][i].y, acc[1][i].z, acc[1][i].w};
        #pragma unroll
        for (int l = 0; l < 4; l++){
            // decode
            float spr = softplus_log2(ya[l]) * LN2;   // softplus value (= 1/rate)
            float lr2 = -lg2f(spr);                   // log2(rate)
            float v   = softplus_log2(yb[l]) * LN2;   // v
            // Z = sum_j exp(j*log_rate - v*ln(j!)) = sum_j 2^(j*lr2 - v*log2(j!))
            float Z = 1.0f + ex2f(lr2);               // j=0,1
            #pragma unroll
            for (int j = 2; j < 20; j++)
                Z += ex2f(fmaf((float)j, lr2, -v * LG2F[j]));
            float lnZ = LN2 * lg2f(Z);
            float log_rate = lr2 * LN2;
            float d = dv[l];
            float lgfd = c_LGF[(int)d];
            // -logpmf = lnZ + v*ln(d!) - d*log_rate
            s += fmaf(v, lgfd, lnZ) - d * log_rate;
        }
    }

    // combine 8 lanes of the same row (lanes tid&7 within contiguous group)
    s += __shfl_xor_sync(0xffffffffu, s, 1);
    s += __shfl_xor_sync(0xffffffffu, s, 2);
    s += __shfl_xor_sync(0xffffffffu, s, 4);
    if (lane8 == 0) g_part[cb][rowg] = s;
}

// ===========================================================================
// K3: finalize — sum 4 colblock partials, divide by XDIM
// ===========================================================================
__global__ void k3_final(float* __restrict__ out)
{
    int row = blockIdx.x * 256 + threadIdx.x;
    float s = g_part[0][row] + g_part[1][row] + g_part[2][row] + g_part[3][row];
    out[row] = s * (1.0f / 1024.0f);
}

// ===========================================================================
extern "C" void kernel_launch(void* const* d_in, const int* in_sizes, int n_in,
                              void* d_out, int out_size)
{
    const float* w    = (const float*)d_in[0];
    const float* data = (const float*)d_in[1];
    const float* W1r  = (const float*)d_in[2];
    const float* b1r  = (const float*)d_in[3];
    const float* W2r  = (const float*)d_in[4];
    const float* b2r  = (const float*)d_in[5];
    const float* W3r  = (const float*)d_in[6];
    const float* b3r  = (const float*)d_in[7];
    const float* W1v  = (const float*)d_in[8];
    const float* b1v  = (const float*)d_in[9];
    const float* W2v  = (const float*)d_in[10];
    const float* b2v  = (const float*)d_in[11];
    const float* W3v  = (const float*)d_in[12];
    const float* b3v  = (const float*)d_in[13];
    float* out = (float*)d_out;

    static bool attr_set = false;
    if (!attr_set){
        cudaFuncSetAttribute(k1_mlp12, cudaFuncAttributeMaxDynamicSharedMemorySize,
                             K1_SMEM_FLOATS * (int)sizeof(float));
        cudaFuncSetAttribute(k2_layer3, cudaFuncAttributeMaxDynamicSharedMemorySize,
                             K2_SMEM_FLOATS * (int)sizeof(float));
        attr_set = true;
    }

    k1_mlp12<<<R_TOTAL/64, 256, K1_SMEM_FLOATS * sizeof(float)>>>(
        w, W1r, b1r, W2r, b2r, W1v, b1v, W2v, b2v);

    dim3 g2(R_TOTAL/32, 4);
    k2_layer3<<<g2, 256, K2_SMEM_FLOATS * sizeof(float)>>>(
        data, W3r, b3r, W3v, b3v);

    k3_final<<<R_TOTAL/256, 256>>>(out);
}

// round 3
// speedup vs baseline: 2.5330x; 2.5330x over previous
#include <cuda_runtime.h>
#include <cuda_bf16.h>

#define R_TOTAL 65536   // T*B = 2048*32
#define XDIM    1024

// ---- scratch (static device arrays; no allocation) ----
__device__ float g_h2[(size_t)R_TOTAL * 128];   // [row][mlp(2)][64]   32 MB
__device__ float g_part[4][R_TOTAL];            // per-colblock partial row sums

// ln(d!) for d = 0..9 (data values are integers 0..9)
__constant__ float c_LGF[10] = {
    0.0f, 0.0f, 0.6931471805599453f, 1.791759469228055f, 3.1780538303479458f,
    4.787491742782046f, 6.579251212010101f, 8.525161361065415f,
    10.604602902745251f, 12.801827480081469f
};

__device__ __forceinline__ float ex2f(float x){ float r; asm("ex2.approx.f32 %0, %1;" : "=f"(r) : "f"(x)); return r; }
__device__ __forceinline__ float lg2f(float x){ float r; asm("lg2.approx.f32 %0, %1;" : "=f"(r) : "f"(x)); return r; }

__device__ __forceinline__ float tanh_fast(float x){
    float xc = fminf(fmaxf(x, -9.0f), 9.0f);
    float e  = ex2f(xc * 2.885390081777927f);   // e^{2x}
    return __fdividef(e - 1.0f, e + 1.0f);
}

// log2(1 + e^y), numerically stable
__device__ __forceinline__ float softplus_log2(float y){
    float t = y * 1.4426950408889634f;
    return fmaxf(t, 0.0f) + lg2f(1.0f + ex2f(-fabsf(t)));
}

// packed f32x2 fma: d = a*b + d (elementwise on 2 packed floats)
__device__ __forceinline__ void ffma2(unsigned long long &d,
                                      unsigned long long a, unsigned long long b){
    asm("fma.rn.f32x2 %0, %1, %2, %0;" : "+l"(d) : "l"(a), "l"(b));
}
__device__ __forceinline__ unsigned long long pack2(float f0, float f1){
    return ((unsigned long long)__float_as_uint(f1) << 32) | (unsigned long long)__float_as_uint(f0);
}
__device__ __forceinline__ float unpk_lo(unsigned long long u){ return __uint_as_float((unsigned)u); }
__device__ __forceinline__ float unpk_hi(unsigned long long u){ return __uint_as_float((unsigned)(u >> 32)); }

// ===========================================================================
// K1: layers 1+2 for both MLPs. 64 rows per block, 256 threads. (unchanged)
// ===========================================================================
#define K1_XSH   0
#define K1_H1SH  (64*32)
#define K1_W2SH  (K1_H1SH + 2*64*257)
#define K1_SMEM_FLOATS (K1_W2SH + 2*64*64)

__global__ void __launch_bounds__(256, 1) k1_mlp12(
    const float* __restrict__ w,
    const float* __restrict__ W1r, const float* __restrict__ b1r,
    const float* __restrict__ W2r, const float* __restrict__ b2r,
    const float* __restrict__ W1v, const float* __restrict__ b1v,
    const float* __restrict__ W2v, const float* __restrict__ b2v)
{
    extern __shared__ float sm[];
    float* xsh  = sm + K1_XSH;
    float* h1sh = sm + K1_H1SH;
    float* w2sh = sm + K1_W2SH;

    const int tid  = threadIdx.x;
    const int row0 = blockIdx.x * 64;

    {
        const float4* src = (const float4*)(w + (size_t)row0 * 32);
        float4* dst = (float4*)xsh;
        for (int i = tid; i < 64*32/4; i += 256) dst[i] = src[i];
    }

    const int c = tid;
    float w1a[16], w1b[16];
    #pragma unroll
    for (int k = 0; k < 16; k++){ w1a[k] = W1r[k*256 + c]; w1b[k] = W1v[k*256 + c]; }
    const float ba = b1r[c], bb = b1v[c];
    __syncthreads();

    #pragma unroll 4
    for (int r = 0; r < 64; r++){
        float xr[32];
        #pragma unroll
        for (int q = 0; q < 8; q++) *(float4*)&xr[q*4] = *(float4*)&xsh[r*32 + q*4];
        float a0 = ba, a1 = bb;
        #pragma unroll
        for (int k = 0; k < 8; k++){
            a0 = fmaf(xr[k],      w1a[k],     a0);
            a0 = fmaf(xr[k + 16], w1a[k + 8], a0);
            a1 = fmaf(xr[k + 8],  w1b[k],     a1);
            a1 = fmaf(xr[k + 24], w1b[k + 8], a1);
        }
        h1sh[(0*64 + r)*257 + c] = tanh_fast(a0);
        h1sh[(1*64 + r)*257 + c] = tanh_fast(a1);
    }

    const int ci = tid & 15, rg = tid >> 4;
    const int c0 = ci * 4,  r0 = rg * 4;

    float acc[2][4][4];
    {
        float4 br = *(const float4*)&b2r[c0];
        float4 bv = *(const float4*)&b2v[c0];
        #pragma unroll
        for (int rr = 0; rr < 4; rr++){
            acc[0][rr][0]=br.x; acc[0][rr][1]=br.y; acc[0][rr][2]=br.z; acc[0][rr][3]=br.w;
            acc[1][rr][0]=bv.x; acc[1][rr][1]=bv.y; acc[1][rr][2]=bv.z; acc[1][rr][3]=bv.w;
        }
    }

    for (int kc = 0; kc < 4; kc++){
        __syncthreads();
        for (int q = tid; q < 2048; q += 256){
            int m   = q >> 10;
            int rem = q & 1023;
            int kk  = rem >> 4;
            int cq  = rem & 15;
            const float* W2m = m ? W2v : W2r;
            *(float4*)&w2sh[(m*64 + kk)*64 + cq*4] =
                *(const float4*)&W2m[(kc*64 + kk)*64 + cq*4];
        }
        __syncthreads();
        #pragma unroll 8
        for (int kk = 0; kk < 64; kk++){
            const int k = kc*64 + kk;
            float4 wr = *(float4*)&w2sh[(0*64 + kk)*64 + c0];
            float4 wv = *(float4*)&w2sh[(1*64 + kk)*64 + c0];
            #pragma unroll
            for (int rr = 0; rr < 4; rr++){
                float h0 = h1sh[(0*64 + r0 + rr)*257 + k];
                float h1 = h1sh[(1*64 + r0 + rr)*257 + k];
                acc[0][rr][0] = fmaf(h0, wr.x, acc[0][rr][0]);
                acc[0][rr][1] = fmaf(h0, wr.y, acc[0][rr][1]);
                acc[0][rr][2] = fmaf(h0, wr.z, acc[0][rr][2]);
                acc[0][rr][3] = fmaf(h0, wr.w, acc[0][rr][3]);
                acc[1][rr][0] = fmaf(h1, wv.x, acc[1][rr][0]);
                acc[1][rr][1] = fmaf(h1, wv.y, acc[1][rr][1]);
                acc[1][rr][2] = fmaf(h1, wv.z, acc[1][rr][2]);
                acc[1][rr][3] = fmaf(h1, wv.w, acc[1][rr][3]);
            }
        }
    }

    #pragma unroll
    for (int m = 0; m < 2; m++){
        #pragma unroll
        for (int rr = 0; rr < 4; rr++){
            float4 o;
            o.x = tanh_fast(acc[m][rr][0]);
            o.y = tanh_fast(acc[m][rr][1]);
            o.z = tanh_fast(acc[m][rr][2]);
            o.w = tanh_fast(acc[m][rr][3]);
            *(float4*)&g_h2[((size_t)(row0 + r0 + rr)*2 + m)*64 + c0] = o;
        }
    }
}

// ===========================================================================
// K2: layer 3 (register-tiled, f32x2) + decode + Z + logpmf + reduction.
// Block = 32 rows x 256 cols, grid = (2048, 4 colblocks). 256 threads.
// Warp wid owns rows row0+wid*4 .. +3 (uniform across lanes).
// Thread lane owns cols: cb*256 + g*128 + lane*4 + {0..3}, g=0,1  (Ct=8).
// smem: h2p (ull, duplicated pairs) [32][2][64] = 32KB | w3sh [2][64][256] = 128KB
// ===========================================================================
#define K2_SMEM_BYTES (32*2*64*8 + 2*64*256*4)

__global__ void __launch_bounds__(256, 1) k2_layer3(
    const float* __restrict__ data,
    const float* __restrict__ W3r, const float* __restrict__ b3r,
    const float* __restrict__ W3v, const float* __restrict__ b3v)
{
    extern __shared__ __align__(16) char smraw[];
    unsigned long long* h2p = (unsigned long long*)smraw;       // 4096 ull
    float* w3sh = (float*)(smraw + 32*2*64*8);                  // 32768 floats

    const int tid  = threadIdx.x;
    const int row0 = blockIdx.x * 32;
    const int cb   = blockIdx.y;           // colblock (256 cols each)
    const int wid  = tid >> 5;
    const int lane = tid & 31;

    // stage h2 as duplicated (h,h) pairs: h2p[rowLocal*128 + m*64 + k]
    for (int q = tid; q < 4096; q += 256){
        int rr  = q >> 7;
        int rem = q & 127;                 // m*64 + k
        unsigned int b = __float_as_uint(g_h2[(size_t)(row0 + rr)*128 + rem]);
        h2p[rr*128 + rem] = ((unsigned long long)b << 32) | (unsigned long long)b;
    }
    // stage W3 col-tile: w3sh[m][k][256] (float4 granularity)
    {
        float4* dst = (float4*)w3sh;
        const float4* s0 = (const float4*)W3r;
        const float4* s1 = (const float4*)W3v;
        for (int q = tid; q < 8192; q += 256){
            int m  = q >> 12;
            int kk = (q >> 6) & 63;
            int cf = q & 63;
            dst[q] = (m ? s1 : s0)[kk*256 + cb*64 + cf];
        }
    }
    __syncthreads();

    // accumulators: acc[m][rr][g*2+p], each ull = 2 packed cols
    unsigned long long acc[2][4][4];
    {
        const float4* br4 = (const float4*)b3r;
        const float4* bv4 = (const float4*)b3v;
        #pragma unroll
        for (int g = 0; g < 2; g++){
            float4 br = br4[cb*64 + g*32 + lane];
            float4 bv = bv4[cb*64 + g*32 + lane];
            #pragma unroll
            for (int rr = 0; rr < 4; rr++){
                acc[0][rr][g*2+0] = pack2(br.x, br.y);
                acc[0][rr][g*2+1] = pack2(br.z, br.w);
                acc[1][rr][g*2+0] = pack2(bv.x, bv.y);
                acc[1][rr][g*2+1] = pack2(bv.z, bv.w);
            }
        }
    }

    // GEMM over K=64
    const ulonglong2* w3u = (const ulonglong2*)w3sh;   // [m*64+k]*64 + colf4
    const unsigned long long* h2row = h2p + wid*4*128;
    #pragma unroll 4
    for (int k = 0; k < 64; k++){
        ulonglong2 w0r = w3u[(size_t)k*64 + lane];          // m=0, g=0
        ulonglong2 w1r = w3u[(size_t)k*64 + 32 + lane];     // m=0, g=1
        ulonglong2 w0v = w3u[(size_t)(64 + k)*64 + lane];   // m=1, g=0
        ulonglong2 w1v = w3u[(size_t)(64 + k)*64 + 32 + lane];
        #pragma unroll
        for (int rr = 0; rr < 4; rr++){
            unsigned long long h0 = h2row[rr*128 + k];
            unsigned long long h1 = h2row[rr*128 + 64 + k];
            ffma2(acc[0][rr][0], h0, w0r.x);
            ffma2(acc[0][rr][1], h0, w0r.y);
            ffma2(acc[0][rr][2], h0, w1r.x);
            ffma2(acc[0][rr][3], h0, w1r.y);
            ffma2(acc[1][rr][0], h1, w0v.x);
            ffma2(acc[1][rr][1], h1, w0v.y);
            ffma2(acc[1][rr][2], h1, w1v.x);
            ffma2(acc[1][rr][3], h1, w1v.y);
        }
    }

    // ---- fused elementwise + reduction ----
    const float LG2F[20] = {
        0.0f, 0.0f, 1.0f, 2.584962500721156f, 4.584962500721156f,
        6.906890595608519f, 9.491853096329675f, 12.299208018387276f,
        15.299208018387276f, 18.469133208679456f, 21.791061114716956f,
        25.250492704179430f, 28.835455204900587f, 32.535894893085060f,
        36.343249797356830f, 40.250140418953415f, 44.250140418953415f,
        48.337603188711560f, 52.507528197247871f, 56.755455722893512f
    };
    const float LN2 = 0.6931471805599453f;
    float srow[4] = {0.f, 0.f, 0.f, 0.f};

    #pragma unroll
    for (int rr = 0; rr < 4; rr++){
        const int rowg = row0 + wid*4 + rr;
        #pragma unroll
        for (int g = 0; g < 2; g++){
            float4 d4 = *(const float4*)&data[(size_t)rowg*1024 + cb*256 + g*128 + lane*4];
            float dv[4] = {d4.x, d4.y, d4.z, d4.w};
            float ya[4] = {unpk_lo(acc[0][rr][g*2]),   unpk_hi(acc[0][rr][g*2]),
                           unpk_lo(acc[0][rr][g*2+1]), unpk_hi(acc[0][rr][g*2+1])};
            float yb[4] = {unpk_lo(acc[1][rr][g*2]),   unpk_hi(acc[1][rr][g*2]),
                           unpk_lo(acc[1][rr][g*2+1]), unpk_hi(acc[1][rr][g*2+1])};
            #pragma unroll
            for (int l = 0; l < 4; l++){
                float spr = softplus_log2(ya[l]) * LN2;   // softplus = 1/rate
                float lr2 = -lg2f(spr);                   // log2(rate)
                float v   = softplus_log2(yb[l]) * LN2;   // v
                float Z = 1.0f + ex2f(lr2);
                #pragma unroll
                for (int j = 2; j < 20; j++)
                    Z += ex2f(fmaf((float)j, lr2, -v * LG2F[j]));
                float lnZ = LN2 * lg2f(Z);
                float log_rate = lr2 * LN2;
                float d = dv[l];
                float lgfd = c_LGF[(int)d];
                srow[rr] += fmaf(v, lgfd, lnZ) - d * log_rate;
            }
        }
    }

    // reduce each row-partial across the warp's 32 lanes
    #pragma unroll
    for (int rr = 0; rr < 4; rr++){
        float s = srow[rr];
        s += __shfl_xor_sync(0xffffffffu, s, 1);
        s += __shfl_xor_sync(0xffffffffu, s, 2);
        s += __shfl_xor_sync(0xffffffffu, s, 4);
        s += __shfl_xor_sync(0xffffffffu, s, 8);
        s += __shfl_xor_sync(0xffffffffu, s, 16);
        srow[rr] = s;
    }
    if (lane == 0){
        #pragma unroll
        for (int rr = 0; rr < 4; rr++)
            g_part[cb][row0 + wid*4 + rr] = srow[rr];
    }
}

// ===========================================================================
// K3: finalize
// ===========================================================================
__global__ void k3_final(float* __restrict__ out)
{
    int row = blockIdx.x * 256 + threadIdx.x;
    float s = g_part[0][row] + g_part[1][row] + g_part[2][row] + g_part[3][row];
    out[row] = s * (1.0f / 1024.0f);
}

// ===========================================================================
extern "C" void kernel_launch(void* const* d_in, const int* in_sizes, int n_in,
                              void* d_out, int out_size)
{
    const float* w    = (const float*)d_in[0];
    const float* data = (const float*)d_in[1];
    const float* W1r  = (const float*)d_in[2];
    const float* b1r  = (const float*)d_in[3];
    const float* W2r  = (const float*)d_in[4];
    const float* b2r  = (const float*)d_in[5];
    const float* W3r  = (const float*)d_in[6];
    const float* b3r  = (const float*)d_in[7];
    const float* W1v  = (const float*)d_in[8];
    const float* b1v  = (const float*)d_in[9];
    const float* W2v  = (const float*)d_in[10];
    const float* b2v  = (const float*)d_in[11];
    const float* W3v  = (const float*)d_in[12];
    const float* b3v  = (const float*)d_in[13];
    float* out = (float*)d_out;

    static bool attr_set = false;
    if (!attr_set){
        cudaFuncSetAttribute(k1_mlp12, cudaFuncAttributeMaxDynamicSharedMemorySize,
                             K1_SMEM_FLOATS * (int)sizeof(float));
        cudaFuncSetAttribute(k2_layer3, cudaFuncAttributeMaxDynamicSharedMemorySize,
                             K2_SMEM_BYTES);
        attr_set = true;
    }

    k1_mlp12<<<R_TOTAL/64, 256, K1_SMEM_FLOATS * sizeof(float)>>>(
        w, W1r, b1r, W2r, b2r, W1v, b1v, W2v, b2v);

    dim3 g2(R_TOTAL/32, 4);
    k2_layer3<<<g2, 256, K2_SMEM_BYTES>>>(
        data, W3r, b3r, W3v, b3v);

    k3_final<<<R_TOTAL/256, 256>>>(out);
}

// round 4
// speedup vs baseline: 2.8547x; 1.1270x over previous
#include <cuda_runtime.h>
#include <cuda_bf16.h>

#define R_TOTAL 65536   // T*B = 2048*32
#define XDIM    1024

// ---- scratch (static device arrays; no allocation) ----
__device__ float g_h2[(size_t)R_TOTAL * 128];   // [row][mlp(2)][64]   32 MB
__device__ float g_part[8][R_TOTAL];            // per-colblock partial row sums

// ln(d!) for d = 0..9 (data values are integers 0..9)
__constant__ float c_LGF[10] = {
    0.0f, 0.0f, 0.6931471805599453f, 1.791759469228055f, 3.1780538303479458f,
    4.787491742782046f, 6.579251212010101f, 8.525161361065415f,
    10.604602902745251f, 12.801827480081469f
};

__device__ __forceinline__ float ex2f(float x){ float r; asm("ex2.approx.f32 %0, %1;" : "=f"(r) : "f"(x)); return r; }
__device__ __forceinline__ float lg2f(float x){ float r; asm("lg2.approx.f32 %0, %1;" : "=f"(r) : "f"(x)); return r; }

__device__ __forceinline__ float tanh_fast(float x){
    float xc = fminf(fmaxf(x, -9.0f), 9.0f);
    float e  = ex2f(xc * 2.885390081777927f);   // e^{2x}
    return __fdividef(e - 1.0f, e + 1.0f);
}

// log2(1 + e^y), numerically stable
__device__ __forceinline__ float softplus_log2(float y){
    float t = y * 1.4426950408889634f;
    return fmaxf(t, 0.0f) + lg2f(1.0f + ex2f(-fabsf(t)));
}

// packed f32x2 fma: d = a*b + d
__device__ __forceinline__ void ffma2(unsigned long long &d,
                                      unsigned long long a, unsigned long long b){
    asm("fma.rn.f32x2 %0, %1, %2, %0;" : "+l"(d) : "l"(a), "l"(b));
}
__device__ __forceinline__ unsigned long long pack2(float f0, float f1){
    return ((unsigned long long)__float_as_uint(f1) << 32) | (unsigned long long)__float_as_uint(f0);
}
__device__ __forceinline__ float unpk_lo(unsigned long long u){ return __uint_as_float((unsigned)u); }
__device__ __forceinline__ float unpk_hi(unsigned long long u){ return __uint_as_float((unsigned)(u >> 32)); }

// ===========================================================================
// K1: layers 1+2 for both MLPs. 32 rows per block, 256 threads, 2 CTAs/SM.
// smem: xsh[32*32] | h1sh[2*32*257] | w2sh[2*64*64]  = 102.7 KB
// ===========================================================================
#define K1_XSH   0
#define K1_H1SH  (32*32)
#define K1_W2SH  (K1_H1SH + 2*32*257)
#define K1_SMEM_FLOATS (K1_W2SH + 2*64*64)

__global__ void __launch_bounds__(256, 2) k1_mlp12(
    const float* __restrict__ w,
    const float* __restrict__ W1r, const float* __restrict__ b1r,
    const float* __restrict__ W2r, const float* __restrict__ b2r,
    const float* __restrict__ W1v, const float* __restrict__ b1v,
    const float* __restrict__ W2v, const float* __restrict__ b2v)
{
    extern __shared__ float sm[];
    float* xsh  = sm + K1_XSH;
    float* h1sh = sm + K1_H1SH;
    float* w2sh = sm + K1_W2SH;

    const int tid  = threadIdx.x;
    const int row0 = blockIdx.x * 32;

    {
        const float4* src = (const float4*)(w + (size_t)row0 * 32);
        float4* dst = (float4*)xsh;
        for (int i = tid; i < 32*32/4; i += 256) dst[i] = src[i];
    }

    // ---- layer 1: thread owns output col c for both MLPs ----
    const int c = tid;
    float w1a[16], w1b[16];
    #pragma unroll
    for (int k = 0; k < 16; k++){ w1a[k] = W1r[k*256 + c]; w1b[k] = W1v[k*256 + c]; }
    const float ba = b1r[c], bb = b1v[c];
    __syncthreads();

    #pragma unroll 4
    for (int r = 0; r < 32; r++){
        float xr[32];
        #pragma unroll
        for (int q = 0; q < 8; q++) *(float4*)&xr[q*4] = *(float4*)&xsh[r*32 + q*4];
        float a0 = ba, a1 = bb;
        #pragma unroll
        for (int k = 0; k < 8; k++){
            a0 = fmaf(xr[k],      w1a[k],     a0);
            a0 = fmaf(xr[k + 16], w1a[k + 8], a0);
            a1 = fmaf(xr[k + 8],  w1b[k],     a1);
            a1 = fmaf(xr[k + 24], w1b[k + 8], a1);
        }
        h1sh[(0*32 + r)*257 + c] = tanh_fast(a0);
        h1sh[(1*32 + r)*257 + c] = tanh_fast(a1);
    }

    // ---- layer 2: thread tile = 2 rows x 4 cols x 2 mlps ----
    const int ci = tid & 15, rg = tid >> 4;
    const int c0 = ci * 4,  r0 = rg * 2;

    float acc[2][2][4];
    {
        float4 br = *(const float4*)&b2r[c0];
        float4 bv = *(const float4*)&b2v[c0];
        #pragma unroll
        for (int rr = 0; rr < 2; rr++){
            acc[0][rr][0]=br.x; acc[0][rr][1]=br.y; acc[0][rr][2]=br.z; acc[0][rr][3]=br.w;
            acc[1][rr][0]=bv.x; acc[1][rr][1]=bv.y; acc[1][rr][2]=bv.z; acc[1][rr][3]=bv.w;
        }
    }

    for (int kc = 0; kc < 4; kc++){      // K = 256 in chunks of 64
        __syncthreads();
        for (int q = tid; q < 2048; q += 256){   // stage W2 chunk [2][64][64] (float4)
            int m   = q >> 10;
            int rem = q & 1023;
            int kk  = rem >> 4;
            int cq  = rem & 15;
            const float* W2m = m ? W2v : W2r;
            *(float4*)&w2sh[(m*64 + kk)*64 + cq*4] =
                *(const float4*)&W2m[(kc*64 + kk)*64 + cq*4];
        }
        __syncthreads();
        #pragma unroll 8
        for (int kk = 0; kk < 64; kk++){
            const int k = kc*64 + kk;
            float4 wr = *(float4*)&w2sh[(0*64 + kk)*64 + c0];
            float4 wv = *(float4*)&w2sh[(1*64 + kk)*64 + c0];
            #pragma unroll
            for (int rr = 0; rr < 2; rr++){
                float h0 = h1sh[(0*32 + r0 + rr)*257 + k];
                float h1 = h1sh[(1*32 + r0 + rr)*257 + k];
                acc[0][rr][0] = fmaf(h0, wr.x, acc[0][rr][0]);
                acc[0][rr][1] = fmaf(h0, wr.y, acc[0][rr][1]);
                acc[0][rr][2] = fmaf(h0, wr.z, acc[0][rr][2]);
                acc[0][rr][3] = fmaf(h0, wr.w, acc[0][rr][3]);
                acc[1][rr][0] = fmaf(h1, wv.x, acc[1][rr][0]);
                acc[1][rr][1] = fmaf(h1, wv.y, acc[1][rr][1]);
                acc[1][rr][2] = fmaf(h1, wv.z, acc[1][rr][2]);
                acc[1][rr][3] = fmaf(h1, wv.w, acc[1][rr][3]);
            }
        }
    }

    #pragma unroll
    for (int m = 0; m < 2; m++){
        #pragma unroll
        for (int rr = 0; rr < 2; rr++){
            float4 o;
            o.x = tanh_fast(acc[m][rr][0]);
            o.y = tanh_fast(acc[m][rr][1]);
            o.z = tanh_fast(acc[m][rr][2]);
            o.w = tanh_fast(acc[m][rr][3]);
            *(float4*)&g_h2[((size_t)(row0 + r0 + rr)*2 + m)*64 + c0] = o;
        }
    }
}

// ===========================================================================
// K2: layer 3 (f32x2 register-tiled) + decode + prime-factored Z + reduction.
// Block = 32 rows x 128 cols, grid = (2048, 8). 256 threads, 2 CTAs/SM.
// Warp wid owns rows row0+wid*4..+3; lane owns cols cb*128 + lane*4 + {0..3}.
// smem: h2p (dup pairs) [32][128] ull = 32KB | w3sh [2][64][128] = 64KB
// ===========================================================================
#define K2_SMEM_BYTES (32*128*8 + 2*64*128*4)

__global__ void __launch_bounds__(256, 2) k2_layer3(
    const float* __restrict__ data,
    const float* __restrict__ W3r, const float* __restrict__ b3r,
    const float* __restrict__ W3v, const float* __restrict__ b3v)
{
    extern __shared__ __align__(16) char smraw[];
    unsigned long long* h2p = (unsigned long long*)smraw;   // 4096 ull
    float* w3sh = (float*)(smraw + 32*128*8);               // 16384 floats

    const int tid  = threadIdx.x;
    const int row0 = blockIdx.x * 32;
    const int cb   = blockIdx.y;          // colblock (128 cols each)
    const int wid  = tid >> 5;
    const int lane = tid & 31;

    // stage h2 as duplicated (h,h) pairs: h2p[rowLocal*128 + m*64 + k]
    for (int q = tid; q < 4096; q += 256){
        int rr  = q >> 7;
        int rem = q & 127;
        unsigned int b = __float_as_uint(g_h2[(size_t)(row0 + rr)*128 + rem]);
        h2p[rr*128 + rem] = ((unsigned long long)b << 32) | (unsigned long long)b;
    }
    // stage W3 col-tile: w3sh[m][k][128] (float4 granularity: 4096 float4)
    {
        float4* dst = (float4*)w3sh;
        const float4* s0 = (const float4*)W3r;
        const float4* s1 = (const float4*)W3v;
        for (int q = tid; q < 4096; q += 256){
            int m  = q >> 11;
            int kk = (q >> 5) & 63;
            int cf = q & 31;
            dst[q] = (m ? s1 : s0)[kk*256 + cb*32 + cf];
        }
    }
    __syncthreads();

    // accumulators: acc[m][rr][p] (p = packed col pair)
    unsigned long long acc[2][4][2];
    {
        const float4* br4 = (const float4*)b3r;
        const float4* bv4 = (const float4*)b3v;
        float4 br = br4[cb*32 + lane];
        float4 bv = bv4[cb*32 + lane];
        #pragma unroll
        for (int rr = 0; rr < 4; rr++){
            acc[0][rr][0] = pack2(br.x, br.y);
            acc[0][rr][1] = pack2(br.z, br.w);
            acc[1][rr][0] = pack2(bv.x, bv.y);
            acc[1][rr][1] = pack2(bv.z, bv.w);
        }
    }

    // GEMM over K=64
    const ulonglong2* w3u = (const ulonglong2*)w3sh;   // [m*64+k]*32 + lane
    const unsigned long long* h2row = h2p + wid*4*128;
    #pragma unroll 4
    for (int k = 0; k < 64; k++){
        ulonglong2 wr = w3u[(size_t)k*32 + lane];          // m=0
        ulonglong2 wv = w3u[(size_t)(64 + k)*32 + lane];   // m=1
        #pragma unroll
        for (int rr = 0; rr < 4; rr++){
            unsigned long long h0 = h2row[rr*128 + k];
            unsigned long long h1 = h2row[rr*128 + 64 + k];
            ffma2(acc[0][rr][0], h0, wr.x);
            ffma2(acc[0][rr][1], h0, wr.y);
            ffma2(acc[1][rr][0], h1, wv.x);
            ffma2(acc[1][rr][1], h1, wv.y);
        }
    }

    // ---- fused elementwise: decode + prime-factored Z + logpmf ----
    const float LN2 = 0.6931471805599453f;
    float srow[4] = {0.f, 0.f, 0.f, 0.f};

    #pragma unroll
    for (int rr = 0; rr < 4; rr++){
        const int rowg = row0 + wid*4 + rr;
        float4 d4 = *(const float4*)&data[(size_t)rowg*1024 + cb*128 + lane*4];
        float dv[4] = {d4.x, d4.y, d4.z, d4.w};
        float ya[4] = {unpk_lo(acc[0][rr][0]), unpk_hi(acc[0][rr][0]),
                       unpk_lo(acc[0][rr][1]), unpk_hi(acc[0][rr][1])};
        float yb[4] = {unpk_lo(acc[1][rr][0]), unpk_hi(acc[1][rr][0]),
                       unpk_lo(acc[1][rr][1]), unpk_hi(acc[1][rr][1])};
        #pragma unroll
        for (int l = 0; l < 4; l++){
            float spr = softplus_log2(ya[l]) * LN2;   // softplus = 1/rate
            float lr2 = -lg2f(spr);                   // log2(rate)
            float v   = softplus_log2(yb[l]) * LN2;   // v
            float rate = ex2f(lr2);

            // prime powers p^{-v} = 2^{-v*log2 p}  (8 MUFU)
            float a2  = ex2f(-v);
            float a3  = ex2f(-v * 1.5849625007211562f);
            float a5  = ex2f(-v * 2.321928094887362f);
            float a7  = ex2f(-v * 2.807354922057604f);
            float a11 = ex2f(-v * 3.4594316186372973f);
            float a13 = ex2f(-v * 3.700439718141092f);
            float a17 = ex2f(-v * 4.087462841250339f);
            float a19 = ex2f(-v * 4.247927513443585f);

            // j^{-v} from prime powers
            float i4  = a2*a2;
            float i9  = a3*a3;
            float i6  = a2*a3;
            float i8  = i4*a2;
            float i10 = a2*a5;
            float i12 = i4*a3;
            float i14 = a2*a7;
            float i15 = a3*a5;
            float i16 = i4*i4;
            float i18 = a2*i9;

            // Z = sum_{j=0..19} rate^j (j!)^{-v}, term_j = term_{j-1} * rate * j^{-v}
            float t = rate;               // j = 1
            float Z = 1.0f + t;
            t *= rate*a2;  Z += t;        // j = 2
            t *= rate*a3;  Z += t;
            t *= rate*i4;  Z += t;
            t *= rate*a5;  Z += t;
            t *= rate*i6;  Z += t;
            t *= rate*a7;  Z += t;
            t *= rate*i8;  Z += t;
            t *= rate*i9;  Z += t;
            t *= rate*i10; Z += t;
            t *= rate*a11; Z += t;
            t *= rate*i12; Z += t;
            t *= rate*a13; Z += t;
            t *= rate*i14; Z += t;
            t *= rate*i15; Z += t;
            t *= rate*i16; Z += t;
            t *= rate*a17; Z += t;
            t *= rate*i18; Z += t;
            t *= rate*a19; Z += t;        // j = 19

            float lnZ = LN2 * lg2f(Z);
            float log_rate = lr2 * LN2;
            float d = dv[l];
            float lgfd = c_LGF[(int)d];
            srow[rr] += fmaf(v, lgfd, lnZ) - d * log_rate;
        }
    }

    // reduce each row-partial across the warp's 32 lanes
    #pragma unroll
    for (int rr = 0; rr < 4; rr++){
        float s = srow[rr];
        s += __shfl_xor_sync(0xffffffffu, s, 1);
        s += __shfl_xor_sync(0xffffffffu, s, 2);
        s += __shfl_xor_sync(0xffffffffu, s, 4);
        s += __shfl_xor_sync(0xffffffffu, s, 8);
        s += __shfl_xor_sync(0xffffffffu, s, 16);
        srow[rr] = s;
    }
    if (lane == 0){
        #pragma unroll
        for (int rr = 0; rr < 4; rr++)
            g_part[cb][row0 + wid*4 + rr] = srow[rr];
    }
}

// ===========================================================================
// K3: finalize — sum 8 colblock partials, divide by XDIM
// ===========================================================================
__global__ void k3_final(float* __restrict__ out)
{
    int row = blockIdx.x * 256 + threadIdx.x;
    float s = 0.0f;
    #pragma unroll
    for (int cb = 0; cb < 8; cb++) s += g_part[cb][row];
    out[row] = s * (1.0f / 1024.0f);
}

// ===========================================================================
extern "C" void kernel_launch(void* const* d_in, const int* in_sizes, int n_in,
                              void* d_out, int out_size)
{
    const float* w    = (const float*)d_in[0];
    const float* data = (const float*)d_in[1];
    const float* W1r  = (const float*)d_in[2];
    const float* b1r  = (const float*)d_in[3];
    const float* W2r  = (const float*)d_in[4];
    const float* b2r  = (const float*)d_in[5];
    const float* W3r  = (const float*)d_in[6];
    const float* b3r  = (const float*)d_in[7];
    const float* W1v  = (const float*)d_in[8];
    const float* b1v  = (const float*)d_in[9];
    const float* W2v  = (const float*)d_in[10];
    const float* b2v  = (const float*)d_in[11];
    const float* W3v  = (const float*)d_in[12];
    const float* b3v  = (const float*)d_in[13];
    float* out = (float*)d_out;

    static bool attr_set = false;
    if (!attr_set){
        cudaFuncSetAttribute(k1_mlp12, cudaFuncAttributeMaxDynamicSharedMemorySize,
                             K1_SMEM_FLOATS * (int)sizeof(float));
        cudaFuncSetAttribute(k2_layer3, cudaFuncAttributeMaxDynamicSharedMemorySize,
                             K2_SMEM_BYTES);
        attr_set = true;
    }

    k1_mlp12<<<R_TOTAL/32, 256, K1_SMEM_FLOATS * sizeof(float)>>>(
        w, W1r, b1r, W2r, b2r, W1v, b1v, W2v, b2v);

    dim3 g2(R_TOTAL/32, 8);
    k2_layer3<<<g2, 256, K2_SMEM_BYTES>>>(
        data, W3r, b3r, W3v, b3v);

    k3_final<<<R_TOTAL/256, 256>>>(out);
}

// round 5
// speedup vs baseline: 3.0657x; 1.0739x over previous
#include <cuda_runtime.h>
#include <cuda_bf16.h>

#define R_TOTAL 65536   // T*B = 2048*32
#define XDIM    1024

// ---- scratch (static device arrays; no allocation) ----
__device__ float g_h2[(size_t)R_TOTAL * 128];   // [row][mlp(2)][64]   32 MB
__device__ float g_part[8][R_TOTAL];            // per-colblock partial row sums

// ln(d!) for d = 0..9 (data values are integers 0..9)
__constant__ float c_LGF[10] = {
    0.0f, 0.0f, 0.6931471805599453f, 1.791759469228055f, 3.1780538303479458f,
    4.787491742782046f, 6.579251212010101f, 8.525161361065415f,
    10.604602902745251f, 12.801827480081469f
};

__device__ __forceinline__ float ex2f(float x){ float r; asm("ex2.approx.f32 %0, %1;" : "=f"(r) : "f"(x)); return r; }
__device__ __forceinline__ float lg2f(float x){ float r; asm("lg2.approx.f32 %0, %1;" : "=f"(r) : "f"(x)); return r; }

__device__ __forceinline__ float tanh_fast(float x){
    float xc = fminf(fmaxf(x, -9.0f), 9.0f);
    float e  = ex2f(xc * 2.885390081777927f);   // e^{2x}
    return __fdividef(e - 1.0f, e + 1.0f);
}

// ---- packed f32x2 helpers ----
typedef unsigned long long ull;
__device__ __forceinline__ void ffma2(ull &d, ull a, ull b){
    asm("fma.rn.f32x2 %0, %1, %2, %0;" : "+l"(d) : "l"(a), "l"(b));
}
__device__ __forceinline__ ull mul2(ull a, ull b){
    ull d; asm("mul.rn.f32x2 %0, %1, %2;" : "=l"(d) : "l"(a), "l"(b)); return d;
}
__device__ __forceinline__ ull add2(ull a, ull b){
    ull d; asm("add.rn.f32x2 %0, %1, %2;" : "=l"(d) : "l"(a), "l"(b)); return d;
}
__device__ __forceinline__ ull pk2(float lo, float hi){
    ull d; asm("mov.b64 %0, {%1, %2};" : "=l"(d) : "f"(lo), "f"(hi)); return d;
}
__device__ __forceinline__ void upk2(float &lo, float &hi, ull u){
    asm("mov.b64 {%0, %1}, %2;" : "=f"(lo), "=f"(hi) : "l"(u));
}
__device__ __forceinline__ ull pack_dup(float f){
    unsigned int b = __float_as_uint(f);
    return ((ull)b << 32) | (ull)b;
}
__device__ __forceinline__ ull pack2i(float f0, float f1){
    return ((ull)__float_as_uint(f1) << 32) | (ull)__float_as_uint(f0);
}

// ===========================================================================
// K1: layers 1+2 for both MLPs. 64 rows per block, 256 threads (round-2 ver).
// ===========================================================================
#define K1_XSH   0
#define K1_H1SH  (64*32)
#define K1_W2SH  (K1_H1SH + 2*64*257)
#define K1_SMEM_FLOATS (K1_W2SH + 2*64*64)

__global__ void __launch_bounds__(256, 1) k1_mlp12(
    const float* __restrict__ w,
    const float* __restrict__ W1r, const float* __restrict__ b1r,
    const float* __restrict__ W2r, const float* __restrict__ b2r,
    const float* __restrict__ W1v, const float* __restrict__ b1v,
    const float* __restrict__ W2v, const float* __restrict__ b2v)
{
    extern __shared__ float sm[];
    float* xsh  = sm + K1_XSH;
    float* h1sh = sm + K1_H1SH;
    float* w2sh = sm + K1_W2SH;

    const int tid  = threadIdx.x;
    const int row0 = blockIdx.x * 64;

    {
        const float4* src = (const float4*)(w + (size_t)row0 * 32);
        float4* dst = (float4*)xsh;
        for (int i = tid; i < 64*32/4; i += 256) dst[i] = src[i];
    }

    const int c = tid;
    float w1a[16], w1b[16];
    #pragma unroll
    for (int k = 0; k < 16; k++){ w1a[k] = W1r[k*256 + c]; w1b[k] = W1v[k*256 + c]; }
    const float ba = b1r[c], bb = b1v[c];
    __syncthreads();

    #pragma unroll 4
    for (int r = 0; r < 64; r++){
        float xr[32];
        #pragma unroll
        for (int q = 0; q < 8; q++) *(float4*)&xr[q*4] = *(float4*)&xsh[r*32 + q*4];
        float a0 = ba, a1 = bb;
        #pragma unroll
        for (int k = 0; k < 8; k++){
            a0 = fmaf(xr[k],      w1a[k],     a0);
            a0 = fmaf(xr[k + 16], w1a[k + 8], a0);
            a1 = fmaf(xr[k + 8],  w1b[k],     a1);
            a1 = fmaf(xr[k + 24], w1b[k + 8], a1);
        }
        h1sh[(0*64 + r)*257 + c] = tanh_fast(a0);
        h1sh[(1*64 + r)*257 + c] = tanh_fast(a1);
    }

    const int ci = tid & 15, rg = tid >> 4;
    const int c0 = ci * 4,  r0 = rg * 4;

    float acc[2][4][4];
    {
        float4 br = *(const float4*)&b2r[c0];
        float4 bv = *(const float4*)&b2v[c0];
        #pragma unroll
        for (int rr = 0; rr < 4; rr++){
            acc[0][rr][0]=br.x; acc[0][rr][1]=br.y; acc[0][rr][2]=br.z; acc[0][rr][3]=br.w;
            acc[1][rr][0]=bv.x; acc[1][rr][1]=bv.y; acc[1][rr][2]=bv.z; acc[1][rr][3]=bv.w;
        }
    }

    for (int kc = 0; kc < 4; kc++){
        __syncthreads();
        for (int q = tid; q < 2048; q += 256){
            int m   = q >> 10;
            int rem = q & 1023;
            int kk  = rem >> 4;
            int cq  = rem & 15;
            const float* W2m = m ? W2v : W2r;
            *(float4*)&w2sh[(m*64 + kk)*64 + cq*4] =
                *(const float4*)&W2m[(kc*64 + kk)*64 + cq*4];
        }
        __syncthreads();
        #pragma unroll 8
        for (int kk = 0; kk < 64; kk++){
            const int k = kc*64 + kk;
            float4 wr = *(float4*)&w2sh[(0*64 + kk)*64 + c0];
            float4 wv = *(float4*)&w2sh[(1*64 + kk)*64 + c0];
            #pragma unroll
            for (int rr = 0; rr < 4; rr++){
                float h0 = h1sh[(0*64 + r0 + rr)*257 + k];
                float h1 = h1sh[(1*64 + r0 + rr)*257 + k];
                acc[0][rr][0] = fmaf(h0, wr.x, acc[0][rr][0]);
                acc[0][rr][1] = fmaf(h0, wr.y, acc[0][rr][1]);
                acc[0][rr][2] = fmaf(h0, wr.z, acc[0][rr][2]);
                acc[0][rr][3] = fmaf(h0, wr.w, acc[0][rr][3]);
                acc[1][rr][0] = fmaf(h1, wv.x, acc[1][rr][0]);
                acc[1][rr][1] = fmaf(h1, wv.y, acc[1][rr][1]);
                acc[1][rr][2] = fmaf(h1, wv.z, acc[1][rr][2]);
                acc[1][rr][3] = fmaf(h1, wv.w, acc[1][rr][3]);
            }
        }
    }

    #pragma unroll
    for (int m = 0; m < 2; m++){
        #pragma unroll
        for (int rr = 0; rr < 4; rr++){
            float4 o;
            o.x = tanh_fast(acc[m][rr][0]);
            o.y = tanh_fast(acc[m][rr][1]);
            o.z = tanh_fast(acc[m][rr][2]);
            o.w = tanh_fast(acc[m][rr][3]);
            *(float4*)&g_h2[((size_t)(row0 + r0 + rr)*2 + m)*64 + c0] = o;
        }
    }
}

// ===========================================================================
// K2: layer 3 (f32x2 GEMM) + decode + prime-factored Z (f32x2) + reduction.
// Block = 32 rows x 128 cols, grid = (2048, 8). 256 threads.
// smem: h2p (dup pairs) [32][128] ull = 32KB | w3sh [2][64][128] = 64KB
// ===========================================================================
#define K2_SMEM_BYTES (32*128*8 + 2*64*128*4)

__global__ void __launch_bounds__(256, 2) k2_layer3(
    const float* __restrict__ data,
    const float* __restrict__ W3r, const float* __restrict__ b3r,
    const float* __restrict__ W3v, const float* __restrict__ b3v)
{
    extern __shared__ __align__(16) char smraw[];
    ull* h2p = (ull*)smraw;                      // 4096 ull
    float* w3sh = (float*)(smraw + 32*128*8);    // 16384 floats

    const int tid  = threadIdx.x;
    const int row0 = blockIdx.x * 32;
    const int cb   = blockIdx.y;          // colblock (128 cols each)
    const int wid  = tid >> 5;
    const int lane = tid & 31;

    // stage h2 as duplicated (h,h) pairs
    for (int q = tid; q < 4096; q += 256){
        int rr  = q >> 7;
        int rem = q & 127;
        h2p[rr*128 + rem] = pack_dup(g_h2[(size_t)(row0 + rr)*128 + rem]);
    }
    // stage W3 col-tile: w3sh[m][k][128] (4096 float4)
    {
        float4* dst = (float4*)w3sh;
        const float4* s0 = (const float4*)W3r;
        const float4* s1 = (const float4*)W3v;
        for (int q = tid; q < 4096; q += 256){
            int m  = q >> 11;
            int kk = (q >> 5) & 63;
            int cf = q & 31;
            dst[q] = (m ? s1 : s0)[kk*256 + cb*32 + cf];
        }
    }
    __syncthreads();

    // accumulators
    ull acc[2][4][2];
    {
        const float4* br4 = (const float4*)b3r;
        const float4* bv4 = (const float4*)b3v;
        float4 br = br4[cb*32 + lane];
        float4 bv = bv4[cb*32 + lane];
        #pragma unroll
        for (int rr = 0; rr < 4; rr++){
            acc[0][rr][0] = pack2i(br.x, br.y);
            acc[0][rr][1] = pack2i(br.z, br.w);
            acc[1][rr][0] = pack2i(bv.x, bv.y);
            acc[1][rr][1] = pack2i(bv.z, bv.w);
        }
    }

    // GEMM over K=64
    const ulonglong2* w3u = (const ulonglong2*)w3sh;
    const ull* h2row = h2p + wid*4*128;
    #pragma unroll 4
    for (int k = 0; k < 64; k++){
        ulonglong2 wr = w3u[(size_t)k*32 + lane];
        ulonglong2 wv = w3u[(size_t)(64 + k)*32 + lane];
        #pragma unroll
        for (int rr = 0; rr < 4; rr++){
            ull h0 = h2row[rr*128 + k];
            ull h1 = h2row[rr*128 + 64 + k];
            ffma2(acc[0][rr][0], h0, wr.x);
            ffma2(acc[0][rr][1], h0, wr.y);
            ffma2(acc[1][rr][0], h1, wv.x);
            ffma2(acc[1][rr][1], h1, wv.y);
        }
    }

    // ---- fused elementwise: packed-pair decode + prime-factored Z ----
    const float LN2   = 0.6931471805599453f;
    const float LOG2E = 1.4426950408889634f;
    const float C_NLG2LN2 = 0.5287663729448977f;   // -log2(ln 2)
    const ull   ONE2 = 0x3F8000003F800000ULL;
    float srow[4] = {0.f, 0.f, 0.f, 0.f};

    #pragma unroll
    for (int rr = 0; rr < 4; rr++){
        const int rowg = row0 + wid*4 + rr;
        float4 d4 = *(const float4*)&data[(size_t)rowg*1024 + cb*128 + lane*4];
        float dvp[2][2] = {{d4.x, d4.y}, {d4.z, d4.w}};

        #pragma unroll
        for (int p = 0; p < 2; p++){
            float ya0, ya1, yb0, yb1;
            upk2(ya0, ya1, acc[0][rr][p]);
            upk2(yb0, yb1, acc[1][rr][p]);

            float lr2h[2], vh[2], rateh[2];
            #pragma unroll
            for (int h = 0; h < 2; h++){
                float ya = h ? ya1 : ya0;
                float yb = h ? yb1 : yb0;
                float ta  = ya * LOG2E;
                float sp2 = fmaxf(ta, 0.0f) + lg2f(1.0f + ex2f(-fabsf(ta)));
                lr2h[h]   = C_NLG2LN2 - lg2f(sp2);           // log2(rate)
                float tb  = yb * LOG2E;
                vh[h]     = LN2 * (fmaxf(tb, 0.0f) + lg2f(1.0f + ex2f(-fabsf(tb))));
                rateh[h]  = ex2f(lr2h[h]);
            }

            // prime powers p^{-v} (scalar MUFU, both halves), then pack
            ull A2  = pk2(ex2f(-vh[0]),                      ex2f(-vh[1]));
            ull A3  = pk2(ex2f(-vh[0]*1.5849625007211562f),  ex2f(-vh[1]*1.5849625007211562f));
            ull A5  = pk2(ex2f(-vh[0]*2.321928094887362f),   ex2f(-vh[1]*2.321928094887362f));
            ull A7  = pk2(ex2f(-vh[0]*2.807354922057604f),   ex2f(-vh[1]*2.807354922057604f));
            ull A11 = pk2(ex2f(-vh[0]*3.4594316186372973f),  ex2f(-vh[1]*3.4594316186372973f));
            ull A13 = pk2(ex2f(-vh[0]*3.700439718141092f),   ex2f(-vh[1]*3.700439718141092f));
            ull A17 = pk2(ex2f(-vh[0]*4.087462841250339f),   ex2f(-vh[1]*4.087462841250339f));
            ull A19 = pk2(ex2f(-vh[0]*4.247927513443585f),   ex2f(-vh[1]*4.247927513443585f));

            // composite j^{-v}
            ull I4  = mul2(A2, A2);
            ull I9  = mul2(A3, A3);
            ull I6  = mul2(A2, A3);
            ull I8  = mul2(I4, A2);
            ull I10 = mul2(A2, A5);
            ull I12 = mul2(I4, A3);
            ull I14 = mul2(A2, A7);
            ull I15 = mul2(A3, A5);
            ull I16 = mul2(I4, I4);
            ull I18 = mul2(A2, I9);

            ull R2 = pk2(rateh[0], rateh[1]);

            // Z recurrence (packed, both elements simultaneously)
            ull t = R2;
            ull Z = add2(ONE2, t);
            t = mul2(t, mul2(R2, A2));  Z = add2(Z, t);
            t = mul2(t, mul2(R2, A3));  Z = add2(Z, t);
            t = mul2(t, mul2(R2, I4));  Z = add2(Z, t);
            t = mul2(t, mul2(R2, A5));  Z = add2(Z, t);
            t = mul2(t, mul2(R2, I6));  Z = add2(Z, t);
            t = mul2(t, mul2(R2, A7));  Z = add2(Z, t);
            t = mul2(t, mul2(R2, I8));  Z = add2(Z, t);
            t = mul2(t, mul2(R2, I9));  Z = add2(Z, t);
            t = mul2(t, mul2(R2, I10)); Z = add2(Z, t);
            t = mul2(t, mul2(R2, A11)); Z = add2(Z, t);
            t = mul2(t, mul2(R2, I12)); Z = add2(Z, t);
            t = mul2(t, mul2(R2, A13)); Z = add2(Z, t);
            t = mul2(t, mul2(R2, I14)); Z = add2(Z, t);
            t = mul2(t, mul2(R2, I15)); Z = add2(Z, t);
            t = mul2(t, mul2(R2, I16)); Z = add2(Z, t);
            t = mul2(t, mul2(R2, A17)); Z = add2(Z, t);
            t = mul2(t, mul2(R2, I18)); Z = add2(Z, t);
            t = mul2(t, mul2(R2, A19)); Z = add2(Z, t);

            float Z0, Z1;
            upk2(Z0, Z1, Z);
            #pragma unroll
            for (int h = 0; h < 2; h++){
                float Zh  = h ? Z1 : Z0;
                float lnZ = LN2 * lg2f(Zh);
                float log_rate = lr2h[h] * LN2;
                float d = dvp[p][h];
                float lgfd = c_LGF[(int)d];
                srow[rr] += fmaf(vh[h], lgfd, lnZ) - d * log_rate;
            }
        }
    }

    // reduce each row-partial across the warp's 32 lanes
    #pragma unroll
    for (int rr = 0; rr < 4; rr++){
        float s = srow[rr];
        s += __shfl_xor_sync(0xffffffffu, s, 1);
        s += __shfl_xor_sync(0xffffffffu, s, 2);
        s += __shfl_xor_sync(0xffffffffu, s, 4);
        s += __shfl_xor_sync(0xffffffffu, s, 8);
        s += __shfl_xor_sync(0xffffffffu, s, 16);
        srow[rr] = s;
    }
    if (lane == 0){
        #pragma unroll
        for (int rr = 0; rr < 4; rr++)
            g_part[cb][row0 + wid*4 + rr] = srow[rr];
    }
}

// ===========================================================================
// K3: finalize
// ===========================================================================
__global__ void k3_final(float* __restrict__ out)
{
    int row = blockIdx.x * 256 + threadIdx.x;
    float s = 0.0f;
    #pragma unroll
    for (int cb = 0; cb < 8; cb++) s += g_part[cb][row];
    out[row] = s * (1.0f / 1024.0f);
}

// ===========================================================================
extern "C" void kernel_launch(void* const* d_in, const int* in_sizes, int n_in,
                              void* d_out, int out_size)
{
    const float* w    = (const float*)d_in[0];
    const float* data = (const float*)d_in[1];
    const float* W1r  = (const float*)d_in[2];
    const float* b1r  = (const float*)d_in[3];
    const float* W2r  = (const float*)d_in[4];
    const float* b2r  = (const float*)d_in[5];
    const float* W3r  = (const float*)d_in[6];
    const float* b3r  = (const float*)d_in[7];
    const float* W1v  = (const float*)d_in[8];
    const float* b1v  = (const float*)d_in[9];
    const float* W2v  = (const float*)d_in[10];
    const float* b2v  = (const float*)d_in[11];
    const float* W3v  = (const float*)d_in[12];
    const float* b3v  = (const float*)d_in[13];
    float* out = (float*)d_out;

    static bool attr_set = false;
    if (!attr_set){
        cudaFuncSetAttribute(k1_mlp12, cudaFuncAttributeMaxDynamicSharedMemorySize,
                             K1_SMEM_FLOATS * (int)sizeof(float));
        cudaFuncSetAttribute(k2_layer3, cudaFuncAttributeMaxDynamicSharedMemorySize,
                             K2_SMEM_BYTES);
        attr_set = true;
    }

    k1_mlp12<<<R_TOTAL/64, 256, K1_SMEM_FLOATS * sizeof(float)>>>(
        w, W1r, b1r, W2r, b2r, W1v, b1v, W2v, b2v);

    dim3 g2(R_TOTAL/32, 8);
    k2_layer3<<<g2, 256, K2_SMEM_BYTES>>>(
        data, W3r, b3r, W3v, b3v);

    k3_final<<<R_TOTAL/256, 256>>>(out);
}

// round 6
// speedup vs baseline: 3.5697x; 1.1644x over previous
#include <cuda_runtime.h>
#include <cuda_bf16.h>

#define R_TOTAL 65536   // T*B = 2048*32
#define XDIM    1024

// ---- scratch (static device arrays; no allocation) ----
__device__ float g_h2[(size_t)R_TOTAL * 128];   // [row][mlp(2)][64]   32 MB
__device__ float g_part[8][R_TOTAL];            // per-colblock partial row sums

// ln(d!) for d = 0..9 (data values are integers 0..9)
__constant__ float c_LGF[10] = {
    0.0f, 0.0f, 0.6931471805599453f, 1.791759469228055f, 3.1780538303479458f,
    4.787491742782046f, 6.579251212010101f, 8.525161361065415f,
    10.604602902745251f, 12.801827480081469f
};

__device__ __forceinline__ float ex2f(float x){ float r; asm("ex2.approx.f32 %0, %1;" : "=f"(r) : "f"(x)); return r; }
__device__ __forceinline__ float lg2f(float x){ float r; asm("lg2.approx.f32 %0, %1;" : "=f"(r) : "f"(x)); return r; }

__device__ __forceinline__ float tanh_fast(float x){
    float xc = fminf(fmaxf(x, -9.0f), 9.0f);
    float e  = ex2f(xc * 2.885390081777927f);   // e^{2x}
    return __fdividef(e - 1.0f, e + 1.0f);
}

// ---- packed f32x2 helpers ----
typedef unsigned long long ull;
__device__ __forceinline__ void ffma2(ull &d, ull a, ull b){
    asm("fma.rn.f32x2 %0, %1, %2, %0;" : "+l"(d) : "l"(a), "l"(b));
}
__device__ __forceinline__ ull mul2(ull a, ull b){
    ull d; asm("mul.rn.f32x2 %0, %1, %2;" : "=l"(d) : "l"(a), "l"(b)); return d;
}
__device__ __forceinline__ ull add2(ull a, ull b){
    ull d; asm("add.rn.f32x2 %0, %1, %2;" : "=l"(d) : "l"(a), "l"(b)); return d;
}
__device__ __forceinline__ ull pk2(float lo, float hi){
    ull d; asm("mov.b64 %0, {%1, %2};" : "=l"(d) : "f"(lo), "f"(hi)); return d;
}
__device__ __forceinline__ void upk2(float &lo, float &hi, ull u){
    asm("mov.b64 {%0, %1}, %2;" : "=f"(lo), "=f"(hi) : "l"(u));
}
__device__ __forceinline__ ull pack_dup(float f){
    unsigned int b = __float_as_uint(f);
    return ((ull)b << 32) | (ull)b;
}
__device__ __forceinline__ ull pack2i(float f0, float f1){
    return ((ull)__float_as_uint(f1) << 32) | (ull)__float_as_uint(f0);
}

// ===========================================================================
// K1: layers 1+2 for both MLPs. 64 rows per block, 256 threads. (unchanged)
// ===========================================================================
#define K1_XSH   0
#define K1_H1SH  (64*32)
#define K1_W2SH  (K1_H1SH + 2*64*257)
#define K1_SMEM_FLOATS (K1_W2SH + 2*64*64)

__global__ void __launch_bounds__(256, 1) k1_mlp12(
    const float* __restrict__ w,
    const float* __restrict__ W1r, const float* __restrict__ b1r,
    const float* __restrict__ W2r, const float* __restrict__ b2r,
    const float* __restrict__ W1v, const float* __restrict__ b1v,
    const float* __restrict__ W2v, const float* __restrict__ b2v)
{
    extern __shared__ float sm[];
    float* xsh  = sm + K1_XSH;
    float* h1sh = sm + K1_H1SH;
    float* w2sh = sm + K1_W2SH;

    const int tid  = threadIdx.x;
    const int row0 = blockIdx.x * 64;

    {
        const float4* src = (const float4*)(w + (size_t)row0 * 32);
        float4* dst = (float4*)xsh;
        for (int i = tid; i < 64*32/4; i += 256) dst[i] = src[i];
    }

    const int c = tid;
    float w1a[16], w1b[16];
    #pragma unroll
    for (int k = 0; k < 16; k++){ w1a[k] = W1r[k*256 + c]; w1b[k] = W1v[k*256 + c]; }
    const float ba = b1r[c], bb = b1v[c];
    __syncthreads();

    #pragma unroll 4
    for (int r = 0; r < 64; r++){
        float xr[32];
        #pragma unroll
        for (int q = 0; q < 8; q++) *(float4*)&xr[q*4] = *(float4*)&xsh[r*32 + q*4];
        float a0 = ba, a1 = bb;
        #pragma unroll
        for (int k = 0; k < 8; k++){
            a0 = fmaf(xr[k],      w1a[k],     a0);
            a0 = fmaf(xr[k + 16], w1a[k + 8], a0);
            a1 = fmaf(xr[k + 8],  w1b[k],     a1);
            a1 = fmaf(xr[k + 24], w1b[k + 8], a1);
        }
        h1sh[(0*64 + r)*257 + c] = tanh_fast(a0);
        h1sh[(1*64 + r)*257 + c] = tanh_fast(a1);
    }

    const int ci = tid & 15, rg = tid >> 4;
    const int c0 = ci * 4,  r0 = rg * 4;

    float acc[2][4][4];
    {
        float4 br = *(const float4*)&b2r[c0];
        float4 bv = *(const float4*)&b2v[c0];
        #pragma unroll
        for (int rr = 0; rr < 4; rr++){
            acc[0][rr][0]=br.x; acc[0][rr][1]=br.y; acc[0][rr][2]=br.z; acc[0][rr][3]=br.w;
            acc[1][rr][0]=bv.x; acc[1][rr][1]=bv.y; acc[1][rr][2]=bv.z; acc[1][rr][3]=bv.w;
        }
    }

    for (int kc = 0; kc < 4; kc++){
        __syncthreads();
        for (int q = tid; q < 2048; q += 256){
            int m   = q >> 10;
            int rem = q & 1023;
            int kk  = rem >> 4;
            int cq  = rem & 15;
            const float* W2m = m ? W2v : W2r;
            *(float4*)&w2sh[(m*64 + kk)*64 + cq*4] =
                *(const float4*)&W2m[(kc*64 + kk)*64 + cq*4];
        }
        __syncthreads();
        #pragma unroll 8
        for (int kk = 0; kk < 64; kk++){
            const int k = kc*64 + kk;
            float4 wr = *(float4*)&w2sh[(0*64 + kk)*64 + c0];
            float4 wv = *(float4*)&w2sh[(1*64 + kk)*64 + c0];
            #pragma unroll
            for (int rr = 0; rr < 4; rr++){
                float h0 = h1sh[(0*64 + r0 + rr)*257 + k];
                float h1 = h1sh[(1*64 + r0 + rr)*257 + k];
                acc[0][rr][0] = fmaf(h0, wr.x, acc[0][rr][0]);
                acc[0][rr][1] = fmaf(h0, wr.y, acc[0][rr][1]);
                acc[0][rr][2] = fmaf(h0, wr.z, acc[0][rr][2]);
                acc[0][rr][3] = fmaf(h0, wr.w, acc[0][rr][3]);
                acc[1][rr][0] = fmaf(h1, wv.x, acc[1][rr][0]);
                acc[1][rr][1] = fmaf(h1, wv.y, acc[1][rr][1]);
                acc[1][rr][2] = fmaf(h1, wv.z, acc[1][rr][2]);
                acc[1][rr][3] = fmaf(h1, wv.w, acc[1][rr][3]);
            }
        }
    }

    #pragma unroll
    for (int m = 0; m < 2; m++){
        #pragma unroll
        for (int rr = 0; rr < 4; rr++){
            float4 o;
            o.x = tanh_fast(acc[m][rr][0]);
            o.y = tanh_fast(acc[m][rr][1]);
            o.z = tanh_fast(acc[m][rr][2]);
            o.w = tanh_fast(acc[m][rr][3]);
            *(float4*)&g_h2[((size_t)(row0 + r0 + rr)*2 + m)*64 + c0] = o;
        }
    }
}

// ===========================================================================
// K2: layer 3 + decode + prime-factored Z + reduction.
// Block = 128 threads (4 warps), 32 rows x 128 cols. grid = (2048, 8).
// Warp wid owns rows row0 + wid*8 .. +7 (Rw=8); lane owns cols lane*4+{0..3}.
// Crossbar/FMA balanced: per 2k-step/warp 32 phases vs 64 FFMA2.
// smem: h2p (dup pairs) [32][128] ull = 32KB | w3sh [2][64][128] f = 64KB
// ===========================================================================
#define K2_SMEM_BYTES (32*128*8 + 2*64*128*4)

__global__ void __launch_bounds__(128, 2) k2_layer3(
    const float* __restrict__ data,
    const float* __restrict__ W3r, const float* __restrict__ b3r,
    const float* __restrict__ W3v, const float* __restrict__ b3v)
{
    extern __shared__ __align__(16) char smraw[];
    ull* h2p = (ull*)smraw;                      // 4096 ull = 32KB
    float* w3sh = (float*)(smraw + 32*128*8);    // 16384 floats = 64KB

    const int tid  = threadIdx.x;
    const int row0 = blockIdx.x * 32;
    const int cb   = blockIdx.y;          // colblock (128 cols each)
    const int wid  = tid >> 5;            // 0..3
    const int lane = tid & 31;

    // stage h2 as duplicated (h,h) pairs: h2p[rowLocal*128 + m*64 + k]
    for (int q = tid; q < 4096; q += 128){
        int rr  = q >> 7;
        int rem = q & 127;
        h2p[rr*128 + rem] = pack_dup(g_h2[(size_t)(row0 + rr)*128 + rem]);
    }
    // stage W3 col-tile: w3sh[m][k][128] (4096 float4)
    {
        float4* dst = (float4*)w3sh;
        const float4* s0 = (const float4*)W3r;
        const float4* s1 = (const float4*)W3v;
        for (int q = tid; q < 4096; q += 128){
            int m  = q >> 11;
            int kk = (q >> 5) & 63;
            int cf = q & 31;
            dst[q] = (m ? s1 : s0)[kk*256 + cb*32 + cf];
        }
    }
    __syncthreads();

    // accumulators: acc[m][rr(8)][p(2)]
    ull acc[2][8][2];
    {
        const float4* br4 = (const float4*)b3r;
        const float4* bv4 = (const float4*)b3v;
        float4 br = br4[cb*32 + lane];
        float4 bv = bv4[cb*32 + lane];
        #pragma unroll
        for (int rr = 0; rr < 8; rr++){
            acc[0][rr][0] = pack2i(br.x, br.y);
            acc[0][rr][1] = pack2i(br.z, br.w);
            acc[1][rr][0] = pack2i(bv.x, bv.y);
            acc[1][rr][1] = pack2i(bv.z, bv.w);
        }
    }

    // GEMM over K=64, k-step 2, paired broadcast h loads
    const ulonglong2* w3u = (const ulonglong2*)w3sh;   // [(m*64+k)*32 + lane]
    const ull* h2row = h2p + wid*8*128;
    #pragma unroll 4
    for (int k = 0; k < 64; k += 2){
        ulonglong2 wr0 = w3u[(size_t)k*32 + lane];
        ulonglong2 wr1 = w3u[(size_t)(k+1)*32 + lane];
        ulonglong2 wv0 = w3u[(size_t)(64 + k)*32 + lane];
        ulonglong2 wv1 = w3u[(size_t)(64 + k + 1)*32 + lane];
        #pragma unroll
        for (int rr = 0; rr < 8; rr++){
            ulonglong2 h0p = *(const ulonglong2*)&h2row[rr*128 + k];        // h0[k], h0[k+1]
            ulonglong2 h1p = *(const ulonglong2*)&h2row[rr*128 + 64 + k];   // h1[k], h1[k+1]
            ffma2(acc[0][rr][0], h0p.x, wr0.x);
            ffma2(acc[0][rr][1], h0p.x, wr0.y);
            ffma2(acc[0][rr][0], h0p.y, wr1.x);
            ffma2(acc[0][rr][1], h0p.y, wr1.y);
            ffma2(acc[1][rr][0], h1p.x, wv0.x);
            ffma2(acc[1][rr][1], h1p.x, wv0.y);
            ffma2(acc[1][rr][0], h1p.y, wv1.x);
            ffma2(acc[1][rr][1], h1p.y, wv1.y);
        }
    }

    // ---- fused elementwise: packed-pair decode + prime-factored Z ----
    const float LN2   = 0.6931471805599453f;
    const float LOG2E = 1.4426950408889634f;
    const float C_NLG2LN2 = 0.5287663729448977f;   // -log2(ln 2)
    const ull   ONE2 = 0x3F8000003F800000ULL;
    float srow[8];
    #pragma unroll
    for (int rr = 0; rr < 8; rr++) srow[rr] = 0.0f;

    #pragma unroll
    for (int rr = 0; rr < 8; rr++){
        const int rowg = row0 + wid*8 + rr;
        float4 d4 = *(const float4*)&data[(size_t)rowg*1024 + cb*128 + lane*4];
        float dvp[2][2] = {{d4.x, d4.y}, {d4.z, d4.w}};

        #pragma unroll
        for (int p = 0; p < 2; p++){
            float ya0, ya1, yb0, yb1;
            upk2(ya0, ya1, acc[0][rr][p]);
            upk2(yb0, yb1, acc[1][rr][p]);

            float lr2h[2], vh[2], rateh[2];
            #pragma unroll
            for (int h = 0; h < 2; h++){
                float ya = h ? ya1 : ya0;
                float yb = h ? yb1 : yb0;
                float ta  = ya * LOG2E;
                float sp2 = fmaxf(ta, 0.0f) + lg2f(1.0f + ex2f(-fabsf(ta)));
                lr2h[h]   = C_NLG2LN2 - lg2f(sp2);           // log2(rate)
                float tb  = yb * LOG2E;
                vh[h]     = LN2 * (fmaxf(tb, 0.0f) + lg2f(1.0f + ex2f(-fabsf(tb))));
                rateh[h]  = ex2f(lr2h[h]);
            }

            // prime powers p^{-v} (scalar MUFU, both halves), then pack
            ull A2  = pk2(ex2f(-vh[0]),                      ex2f(-vh[1]));
            ull A3  = pk2(ex2f(-vh[0]*1.5849625007211562f),  ex2f(-vh[1]*1.5849625007211562f));
            ull A5  = pk2(ex2f(-vh[0]*2.321928094887362f),   ex2f(-vh[1]*2.321928094887362f));
            ull A7  = pk2(ex2f(-vh[0]*2.807354922057604f),   ex2f(-vh[1]*2.807354922057604f));
            ull A11 = pk2(ex2f(-vh[0]*3.4594316186372973f),  ex2f(-vh[1]*3.4594316186372973f));
            ull A13 = pk2(ex2f(-vh[0]*3.700439718141092f),   ex2f(-vh[1]*3.700439718141092f));
            ull A17 = pk2(ex2f(-vh[0]*4.087462841250339f),   ex2f(-vh[1]*4.087462841250339f));
            ull A19 = pk2(ex2f(-vh[0]*4.247927513443585f),   ex2f(-vh[1]*4.247927513443585f));

            // composite j^{-v}
            ull I4  = mul2(A2, A2);
            ull I9  = mul2(A3, A3);
            ull I6  = mul2(A2, A3);
            ull I8  = mul2(I4, A2);
            ull I10 = mul2(A2, A5);
            ull I12 = mul2(I4, A3);
            ull I14 = mul2(A2, A7);
            ull I15 = mul2(A3, A5);
            ull I16 = mul2(I4, I4);
            ull I18 = mul2(A2, I9);

            ull R2 = pk2(rateh[0], rateh[1]);

            // Z recurrence (packed)
            ull t = R2;
            ull Z = add2(ONE2, t);
            t = mul2(t, mul2(R2, A2));  Z = add2(Z, t);
            t = mul2(t, mul2(R2, A3));  Z = add2(Z, t);
            t = mul2(t, mul2(R2, I4));  Z = add2(Z, t);
            t = mul2(t, mul2(R2, A5));  Z = add2(Z, t);
            t = mul2(t, mul2(R2, I6));  Z = add2(Z, t);
            t = mul2(t, mul2(R2, A7));  Z = add2(Z, t);
            t = mul2(t, mul2(R2, I8));  Z = add2(Z, t);
            t = mul2(t, mul2(R2, I9));  Z = add2(Z, t);
            t = mul2(t, mul2(R2, I10)); Z = add2(Z, t);
            t = mul2(t, mul2(R2, A11)); Z = add2(Z, t);
            t = mul2(t, mul2(R2, I12)); Z = add2(Z, t);
            t = mul2(t, mul2(R2, A13)); Z = add2(Z, t);
            t = mul2(t, mul2(R2, I14)); Z = add2(Z, t);
            t = mul2(t, mul2(R2, I15)); Z = add2(Z, t);
            t = mul2(t, mul2(R2, I16)); Z = add2(Z, t);
            t = mul2(t, mul2(R2, A17)); Z = add2(Z, t);
            t = mul2(t, mul2(R2, I18)); Z = add2(Z, t);
            t = mul2(t, mul2(R2, A19)); Z = add2(Z, t);

            float Z0, Z1;
            upk2(Z0, Z1, Z);
            #pragma unroll
            for (int h = 0; h < 2; h++){
                float Zh  = h ? Z1 : Z0;
                float lnZ = LN2 * lg2f(Zh);
                float log_rate = lr2h[h] * LN2;
                float d = dvp[p][h];
                float lgfd = c_LGF[(int)d];
                srow[rr] += fmaf(vh[h], lgfd, lnZ) - d * log_rate;
            }
        }
    }

    // reduce row-partials across the warp's 32 lanes
    #pragma unroll
    for (int rr = 0; rr < 8; rr++){
        float s = srow[rr];
        s += __shfl_xor_sync(0xffffffffu, s, 1);
        s += __shfl_xor_sync(0xffffffffu, s, 2);
        s += __shfl_xor_sync(0xffffffffu, s, 4);
        s += __shfl_xor_sync(0xffffffffu, s, 8);
        s += __shfl_xor_sync(0xffffffffu, s, 16);
        srow[rr] = s;
    }
    if (lane == 0){
        #pragma unroll
        for (int rr = 0; rr < 8; rr++)
            g_part[cb][row0 + wid*8 + rr] = srow[rr];
    }
}

// ===========================================================================
// K3: finalize
// ===========================================================================
__global__ void k3_final(float* __restrict__ out)
{
    int row = blockIdx.x * 256 + threadIdx.x;
    float s = 0.0f;
    #pragma unroll
    for (int cb = 0; cb < 8; cb++) s += g_part[cb][row];
    out[row] = s * (1.0f / 1024.0f);
}

// ===========================================================================
extern "C" void kernel_launch(void* const* d_in, const int* in_sizes, int n_in,
                              void* d_out, int out_size)
{
    const float* w    = (const float*)d_in[0];
    const float* data = (const float*)d_in[1];
    const float* W1r  = (const float*)d_in[2];
    const float* b1r  = (const float*)d_in[3];
    const float* W2r  = (const float*)d_in[4];
    const float* b2r  = (const float*)d_in[5];
    const float* W3r  = (const float*)d_in[6];
    const float* b3r  = (const float*)d_in[7];
    const float* W1v  = (const float*)d_in[8];
    const float* b1v  = (const float*)d_in[9];
    const float* W2v  = (const float*)d_in[10];
    const float* b2v  = (const float*)d_in[11];
    const float* W3v  = (const float*)d_in[12];
    const float* b3v  = (const float*)d_in[13];
    float* out = (float*)d_out;

    static bool attr_set = false;
    if (!attr_set){
        cudaFuncSetAttribute(k1_mlp12, cudaFuncAttributeMaxDynamicSharedMemorySize,
                             K1_SMEM_FLOATS * (int)sizeof(float));
        cudaFuncSetAttribute(k2_layer3, cudaFuncAttributeMaxDynamicSharedMemorySize,
                             K2_SMEM_BYTES);
        attr_set = true;
    }

    k1_mlp12<<<R_TOTAL/64, 256, K1_SMEM_FLOATS * sizeof(float)>>>(
        w, W1r, b1r, W2r, b2r, W1v, b1v, W2v, b2v);

    dim3 g2(R_TOTAL/32, 8);
    k2_layer3<<<g2, 128, K2_SMEM_BYTES>>>(
        data, W3r, b3r, W3v, b3v);

    k3_final<<<R_TOTAL/256, 256>>>(out);
}

// round 7
// speedup vs baseline: 3.8056x; 1.0661x over previous
#include <cuda_runtime.h>
#include <cuda_bf16.h>

#define R_TOTAL 65536   // T*B = 2048*32
#define XDIM    1024

// ---- scratch (static device arrays; no allocation) ----
__device__ float g_h2[(size_t)R_TOTAL * 128];   // [row][mlp(2)][64]   32 MB
__device__ float g_part[8][R_TOTAL];            // per-colblock partial row sums (log2-domain)

__device__ __forceinline__ float ex2f(float x){ float r; asm("ex2.approx.f32 %0, %1;" : "=f"(r) : "f"(x)); return r; }
__device__ __forceinline__ float lg2f(float x){ float r; asm("lg2.approx.f32 %0, %1;" : "=f"(r) : "f"(x)); return r; }

__device__ __forceinline__ float tanh_fast(float x){
    float xc = fminf(fmaxf(x, -9.0f), 9.0f);
    float e  = ex2f(xc * 2.885390081777927f);   // e^{2x}
    return __fdividef(e - 1.0f, e + 1.0f);
}

// ---- packed f32x2 helpers ----
typedef unsigned long long ull;
__device__ __forceinline__ void ffma2(ull &d, ull a, ull b){
    asm("fma.rn.f32x2 %0, %1, %2, %0;" : "+l"(d) : "l"(a), "l"(b));
}
__device__ __forceinline__ ull mul2(ull a, ull b){
    ull d; asm("mul.rn.f32x2 %0, %1, %2;" : "=l"(d) : "l"(a), "l"(b)); return d;
}
__device__ __forceinline__ ull add2(ull a, ull b){
    ull d; asm("add.rn.f32x2 %0, %1, %2;" : "=l"(d) : "l"(a), "l"(b)); return d;
}
__device__ __forceinline__ ull pk2(float lo, float hi){
    ull d; asm("mov.b64 %0, {%1, %2};" : "=l"(d) : "f"(lo), "f"(hi)); return d;
}
__device__ __forceinline__ void upk2(float &lo, float &hi, ull u){
    asm("mov.b64 {%0, %1}, %2;" : "=f"(lo), "=f"(hi) : "l"(u));
}
__device__ __forceinline__ ull pack_dup(float f){
    unsigned int b = __float_as_uint(f);
    return ((ull)b << 32) | (ull)b;
}
__device__ __forceinline__ ull pack2i(float f0, float f1){
    return ((ull)__float_as_uint(f1) << 32) | (ull)__float_as_uint(f0);
}

// ===========================================================================
// K1: layers 1+2 for both MLPs. 64 rows per block, 256 threads. (unchanged)
// ===========================================================================
#define K1_XSH   0
#define K1_H1SH  (64*32)
#define K1_W2SH  (K1_H1SH + 2*64*257)
#define K1_SMEM_FLOATS (K1_W2SH + 2*64*64)

__global__ void __launch_bounds__(256, 1) k1_mlp12(
    const float* __restrict__ w,
    const float* __restrict__ W1r, const float* __restrict__ b1r,
    const float* __restrict__ W2r, const float* __restrict__ b2r,
    const float* __restrict__ W1v, const float* __restrict__ b1v,
    const float* __restrict__ W2v, const float* __restrict__ b2v)
{
    extern __shared__ float sm[];
    float* xsh  = sm + K1_XSH;
    float* h1sh = sm + K1_H1SH;
    float* w2sh = sm + K1_W2SH;

    const int tid  = threadIdx.x;
    const int row0 = blockIdx.x * 64;

    {
        const float4* src = (const float4*)(w + (size_t)row0 * 32);
        float4* dst = (float4*)xsh;
        for (int i = tid; i < 64*32/4; i += 256) dst[i] = src[i];
    }

    const int c = tid;
    float w1a[16], w1b[16];
    #pragma unroll
    for (int k = 0; k < 16; k++){ w1a[k] = W1r[k*256 + c]; w1b[k] = W1v[k*256 + c]; }
    const float ba = b1r[c], bb = b1v[c];
    __syncthreads();

    #pragma unroll 4
    for (int r = 0; r < 64; r++){
        float xr[32];
        #pragma unroll
        for (int q = 0; q < 8; q++) *(float4*)&xr[q*4] = *(float4*)&xsh[r*32 + q*4];
        float a0 = ba, a1 = bb;
        #pragma unroll
        for (int k = 0; k < 8; k++){
            a0 = fmaf(xr[k],      w1a[k],     a0);
            a0 = fmaf(xr[k + 16], w1a[k + 8], a0);
            a1 = fmaf(xr[k + 8],  w1b[k],     a1);
            a1 = fmaf(xr[k + 24], w1b[k + 8], a1);
        }
        h1sh[(0*64 + r)*257 + c] = tanh_fast(a0);
        h1sh[(1*64 + r)*257 + c] = tanh_fast(a1);
    }

    const int ci = tid & 15, rg = tid >> 4;
    const int c0 = ci * 4,  r0 = rg * 4;

    float acc[2][4][4];
    {
        float4 br = *(const float4*)&b2r[c0];
        float4 bv = *(const float4*)&b2v[c0];
        #pragma unroll
        for (int rr = 0; rr < 4; rr++){
            acc[0][rr][0]=br.x; acc[0][rr][1]=br.y; acc[0][rr][2]=br.z; acc[0][rr][3]=br.w;
            acc[1][rr][0]=bv.x; acc[1][rr][1]=bv.y; acc[1][rr][2]=bv.z; acc[1][rr][3]=bv.w;
        }
    }

    for (int kc = 0; kc < 4; kc++){
        __syncthreads();
        for (int q = tid; q < 2048; q += 256){
            int m   = q >> 10;
            int rem = q & 1023;
            int kk  = rem >> 4;
            int cq  = rem & 15;
            const float* W2m = m ? W2v : W2r;
            *(float4*)&w2sh[(m*64 + kk)*64 + cq*4] =
                *(const float4*)&W2m[(kc*64 + kk)*64 + cq*4];
        }
        __syncthreads();
        #pragma unroll 8
        for (int kk = 0; kk < 64; kk++){
            const int k = kc*64 + kk;
            float4 wr = *(float4*)&w2sh[(0*64 + kk)*64 + c0];
            float4 wv = *(float4*)&w2sh[(1*64 + kk)*64 + c0];
            #pragma unroll
            for (int rr = 0; rr < 4; rr++){
                float h0 = h1sh[(0*64 + r0 + rr)*257 + k];
                float h1 = h1sh[(1*64 + r0 + rr)*257 + k];
                acc[0][rr][0] = fmaf(h0, wr.x, acc[0][rr][0]);
                acc[0][rr][1] = fmaf(h0, wr.y, acc[0][rr][1]);
                acc[0][rr][2] = fmaf(h0, wr.z, acc[0][rr][2]);
                acc[0][rr][3] = fmaf(h0, wr.w, acc[0][rr][3]);
                acc[1][rr][0] = fmaf(h1, wv.x, acc[1][rr][0]);
                acc[1][rr][1] = fmaf(h1, wv.y, acc[1][rr][1]);
                acc[1][rr][2] = fmaf(h1, wv.z, acc[1][rr][2]);
                acc[1][rr][3] = fmaf(h1, wv.w, acc[1][rr][3]);
            }
        }
    }

    #pragma unroll
    for (int m = 0; m < 2; m++){
        #pragma unroll
        for (int rr = 0; rr < 4; rr++){
            float4 o;
            o.x = tanh_fast(acc[m][rr][0]);
            o.y = tanh_fast(acc[m][rr][1]);
            o.z = tanh_fast(acc[m][rr][2]);
            o.w = tanh_fast(acc[m][rr][3]);
            *(float4*)&g_h2[((size_t)(row0 + r0 + rr)*2 + m)*64 + c0] = o;
        }
    }
}

// ===========================================================================
// K2: layer 3 + decode + prime-factored Z + reduction.
// Block = 128 threads (4 warps), 32 rows x 128 cols. grid = (2048, 8).
// smem: h2p [32][128] ull = 32KB | w3sh [2][64][128] = 64KB | dsh = 16KB | lut
// ===========================================================================
#define K2_OFF_W3   (32*128*8)             // 32768
#define K2_OFF_DATA (K2_OFF_W3 + 2*64*128*4)   // 98304
#define K2_OFF_LUT  (K2_OFF_DATA + 32*128*4)   // 114688
#define K2_SMEM_BYTES (K2_OFF_LUT + 64)        // 114752

__global__ void __launch_bounds__(128, 2) k2_layer3(
    const float* __restrict__ data,
    const float* __restrict__ W3r, const float* __restrict__ b3r,
    const float* __restrict__ W3v, const float* __restrict__ b3v)
{
    extern __shared__ __align__(16) char smraw[];
    ull*   h2p  = (ull*)smraw;                       // 4096 ull
    float* w3sh = (float*)(smraw + K2_OFF_W3);       // 16384 floats
    float* dsh  = (float*)(smraw + K2_OFF_DATA);     // 4096 floats
    float* lut  = (float*)(smraw + K2_OFF_LUT);      // 10 floats: ln(d!)

    const int tid  = threadIdx.x;
    const int row0 = blockIdx.x * 32;
    const int cb   = blockIdx.y;          // colblock (128 cols each)
    const int wid  = tid >> 5;            // 0..3
    const int lane = tid & 31;

    // ---- cp.async prefetch of the data tile (issued first, waited post-GEMM)
    {
        unsigned int dsh_base = (unsigned int)__cvta_generic_to_shared(dsh);
        #pragma unroll
        for (int i = 0; i < 8; i++){
            int q  = tid + i*128;          // 16B chunk id, 0..1023
            int rr = q >> 5, cf = q & 31;
            const float* src = data + (size_t)(row0 + rr)*1024 + cb*128 + cf*4;
            asm volatile("cp.async.cg.shared.global [%0], [%1], 16;"
                         :: "r"(dsh_base + q*16), "l"(src));
        }
        asm volatile("cp.async.commit_group;");
    }

    if (tid < 10){
        const float LGF[10] = {
            0.0f, 0.0f, 0.6931471805599453f, 1.791759469228055f, 3.1780538303479458f,
            4.787491742782046f, 6.579251212010101f, 8.525161361065415f,
            10.604602902745251f, 12.801827480081469f };
        lut[tid] = LGF[tid];
    }

    // stage h2 as duplicated (h,h) pairs
    for (int q = tid; q < 4096; q += 128){
        int rr  = q >> 7;
        int rem = q & 127;
        h2p[rr*128 + rem] = pack_dup(g_h2[(size_t)(row0 + rr)*128 + rem]);
    }
    // stage W3 col-tile: w3sh[m][k][128] (4096 float4)
    {
        float4* dst = (float4*)w3sh;
        const float4* s0 = (const float4*)W3r;
        const float4* s1 = (const float4*)W3v;
        for (int q = tid; q < 4096; q += 128){
            int m  = q >> 11;
            int kk = (q >> 5) & 63;
            int cf = q & 31;
            dst[q] = (m ? s1 : s0)[kk*256 + cb*32 + cf];
        }
    }
    __syncthreads();

    // accumulators: acc[m][rr(8)][p(2)]
    ull acc[2][8][2];
    {
        const float4* br4 = (const float4*)b3r;
        const float4* bv4 = (const float4*)b3v;
        float4 br = br4[cb*32 + lane];
        float4 bv = bv4[cb*32 + lane];
        #pragma unroll
        for (int rr = 0; rr < 8; rr++){
            acc[0][rr][0] = pack2i(br.x, br.y);
            acc[0][rr][1] = pack2i(br.z, br.w);
            acc[1][rr][0] = pack2i(bv.x, bv.y);
            acc[1][rr][1] = pack2i(bv.z, bv.w);
        }
    }

    // GEMM over K=64, k-step 2, paired broadcast h loads
    const ulonglong2* w3u = (const ulonglong2*)w3sh;
    const ull* h2row = h2p + wid*8*128;
    #pragma unroll 4
    for (int k = 0; k < 64; k += 2){
        ulonglong2 wr0 = w3u[(size_t)k*32 + lane];
        ulonglong2 wr1 = w3u[(size_t)(k+1)*32 + lane];
        ulonglong2 wv0 = w3u[(size_t)(64 + k)*32 + lane];
        ulonglong2 wv1 = w3u[(size_t)(64 + k + 1)*32 + lane];
        #pragma unroll
        for (int rr = 0; rr < 8; rr++){
            ulonglong2 h0p = *(const ulonglong2*)&h2row[rr*128 + k];
            ulonglong2 h1p = *(const ulonglong2*)&h2row[rr*128 + 64 + k];
            ffma2(acc[0][rr][0], h0p.x, wr0.x);
            ffma2(acc[0][rr][1], h0p.x, wr0.y);
            ffma2(acc[0][rr][0], h0p.y, wr1.x);
            ffma2(acc[0][rr][1], h0p.y, wr1.y);
            ffma2(acc[1][rr][0], h1p.x, wv0.x);
            ffma2(acc[1][rr][1], h1p.x, wv0.y);
            ffma2(acc[1][rr][0], h1p.y, wv1.x);
            ffma2(acc[1][rr][1], h1p.y, wv1.y);
        }
    }

    // data prefetch must have landed; make it visible across threads
    asm volatile("cp.async.wait_group 0;");
    __syncthreads();

    // ---- fused elementwise (log2-domain; final LN2 scale in K3) ----
    const float LOG2E = 1.4426950408889634f;
    const float C_NLG2LN2 = 0.5287663729448977f;   // -log2(ln 2)
    const ull   ONE2 = 0x3F8000003F800000ULL;
    // ln(p) constants: exponent of p^{-v} in base-2 is -sp2b * ln(p)
    const float LNP3  = 1.0986122886681098f;
    const float LNP5  = 1.6094379124341003f;
    const float LNP7  = 1.9459101090932196f;
    const float LNP11 = 2.3978952727983707f;
    const float LNP13 = 2.5649493574615367f;
    const float LNP17 = 2.833213344056216f;
    const float LNP19 = 2.9444389791664403f;
    const float LN2c  = 0.6931471805599453f;

    float srow[8];
    #pragma unroll
    for (int rr = 0; rr < 8; rr++) srow[rr] = 0.0f;

    #pragma unroll
    for (int rr = 0; rr < 8; rr++){
        const int rl = wid*8 + rr;              // local row
        float4 d4 = *(const float4*)&dsh[rl*128 + lane*4];
        float dvp[2][2] = {{d4.x, d4.y}, {d4.z, d4.w}};

        #pragma unroll
        for (int p = 0; p < 2; p++){
            float ya0, ya1, yb0, yb1;
            upk2(ya0, ya1, acc[0][rr][p]);
            upk2(yb0, yb1, acc[1][rr][p]);

            float lr2h[2], sbh[2], rateh[2];
            #pragma unroll
            for (int h = 0; h < 2; h++){
                float ya = h ? ya1 : ya0;
                float yb = h ? yb1 : yb0;
                float ta  = ya * LOG2E;
                float spa = fmaxf(ta, 0.0f) + lg2f(1.0f + ex2f(-fabsf(ta)));
                lr2h[h]   = C_NLG2LN2 - lg2f(spa);            // log2(rate)
                float tb  = yb * LOG2E;
                sbh[h]    = fmaxf(tb, 0.0f) + lg2f(1.0f + ex2f(-fabsf(tb)));  // v / ln2
                rateh[h]  = ex2f(lr2h[h]);
            }

            // prime powers p^{-v} = 2^{-sp2b * ln p}
            ull A2  = pk2(ex2f(-sbh[0]*LN2c),  ex2f(-sbh[1]*LN2c));
            ull A3  = pk2(ex2f(-sbh[0]*LNP3),  ex2f(-sbh[1]*LNP3));
            ull A5  = pk2(ex2f(-sbh[0]*LNP5),  ex2f(-sbh[1]*LNP5));
            ull A7  = pk2(ex2f(-sbh[0]*LNP7),  ex2f(-sbh[1]*LNP7));
            ull A11 = pk2(ex2f(-sbh[0]*LNP11), ex2f(-sbh[1]*LNP11));
            ull A13 = pk2(ex2f(-sbh[0]*LNP13), ex2f(-sbh[1]*LNP13));
            ull A17 = pk2(ex2f(-sbh[0]*LNP17), ex2f(-sbh[1]*LNP17));
            ull A19 = pk2(ex2f(-sbh[0]*LNP19), ex2f(-sbh[1]*LNP19));

            ull R = pk2(rateh[0], rateh[1]);

            // B_j = R * j^{-v}
            ull B2  = mul2(R, A2);
            ull B3  = mul2(R, A3);
            ull B5  = mul2(R, A5);
            ull B7  = mul2(R, A7);
            ull B11 = mul2(R, A11);
            ull B13 = mul2(R, A13);
            ull B17 = mul2(R, A17);
            ull B19 = mul2(R, A19);
            ull B4  = mul2(B2, A2);
            ull B6  = mul2(B2, A3);
            ull B8  = mul2(B4, A2);
            ull B9  = mul2(B3, A3);
            ull B10 = mul2(B2, A5);
            ull B12 = mul2(B4, A3);
            ull B14 = mul2(B2, A7);
            ull B15 = mul2(B3, A5);
            ull B16 = mul2(B8, A2);
            ull B18 = mul2(B9, A2);

            // Z: term_j = term_{j-1} * B_j
            ull t = R;                    // j = 1
            ull Z = add2(ONE2, t);
            t = mul2(t, B2);  Z = add2(Z, t);
            t = mul2(t, B3);  Z = add2(Z, t);
            t = mul2(t, B4);  Z = add2(Z, t);
            t = mul2(t, B5);  Z = add2(Z, t);
            t = mul2(t, B6);  Z = add2(Z, t);
            t = mul2(t, B7);  Z = add2(Z, t);
            t = mul2(t, B8);  Z = add2(Z, t);
            t = mul2(t, B9);  Z = add2(Z, t);
            t = mul2(t, B10); Z = add2(Z, t);
            t = mul2(t, B11); Z = add2(Z, t);
            t = mul2(t, B12); Z = add2(Z, t);
            t = mul2(t, B13); Z = add2(Z, t);
            t = mul2(t, B14); Z = add2(Z, t);
            t = mul2(t, B15); Z = add2(Z, t);
            t = mul2(t, B16); Z = add2(Z, t);
            t = mul2(t, B17); Z = add2(Z, t);
            t = mul2(t, B18); Z = add2(Z, t);
            t = mul2(t, B19); Z = add2(Z, t);

            float Z0, Z1;
            upk2(Z0, Z1, Z);
            #pragma unroll
            for (int h = 0; h < 2; h++){
                float Zh  = h ? Z1 : Z0;
                float d   = dvp[p][h];
                float lgfd = lut[(int)d];
                // log2-domain: LN2*(lg2Z - d*lr2 + sp2b*ln(d!)) == lnZ + v*ln(d!) - d*ln(rate)
                float x = fmaf(-d, lr2h[h], lg2f(Zh));
                srow[rr] += fmaf(sbh[h], lgfd, x);
            }
        }
    }

    // reduce row-partials across the warp's 32 lanes
    #pragma unroll
    for (int rr = 0; rr < 8; rr++){
        float s = srow[rr];
        s += __shfl_xor_sync(0xffffffffu, s, 1);
        s += __shfl_xor_sync(0xffffffffu, s, 2);
        s += __shfl_xor_sync(0xffffffffu, s, 4);
        s += __shfl_xor_sync(0xffffffffu, s, 8);
        s += __shfl_xor_sync(0xffffffffu, s, 16);
        srow[rr] = s;
    }
    if (lane == 0){
        #pragma unroll
        for (int rr = 0; rr < 8; rr++)
            g_part[cb][row0 + wid*8 + rr] = srow[rr];
    }
}

// ===========================================================================
// K3: finalize — sum colblock partials, scale by LN2/1024
// ===========================================================================
__global__ void k3_final(float* __restrict__ out)
{
    int row = blockIdx.x * 256 + threadIdx.x;
    float s = 0.0f;
    #pragma unroll
    for (int cb = 0; cb < 8; cb++) s += g_part[cb][row];
    out[row] = s * 6.7690154351557146e-4f;   // ln2 / 1024
}

// ===========================================================================
extern "C" void kernel_launch(void* const* d_in, const int* in_sizes, int n_in,
                              void* d_out, int out_size)
{
    const float* w    = (const float*)d_in[0];
    const float* data = (const float*)d_in[1];
    const float* W1r  = (const float*)d_in[2];
    const float* b1r  = (const float*)d_in[3];
    const float* W2r  = (const float*)d_in[4];
    const float* b2r  = (const float*)d_in[5];
    const float* W3r  = (const float*)d_in[6];
    const float* b3r  = (const float*)d_in[7];
    const float* W1v  = (const float*)d_in[8];
    const float* b1v  = (const float*)d_in[9];
    const float* W2v  = (const float*)d_in[10];
    const float* b2v  = (const float*)d_in[11];
    const float* W3v  = (const float*)d_in[12];
    const float* b3v  = (const float*)d_in[13];
    float* out = (float*)d_out;

    static bool attr_set = false;
    if (!attr_set){
        cudaFuncSetAttribute(k1_mlp12, cudaFuncAttributeMaxDynamicSharedMemorySize,
                             K1_SMEM_FLOATS * (int)sizeof(float));
        cudaFuncSetAttribute(k2_layer3, cudaFuncAttributeMaxDynamicSharedMemorySize,
                             K2_SMEM_BYTES);
        attr_set = true;
    }

    k1_mlp12<<<R_TOTAL/64, 256, K1_SMEM_FLOATS * sizeof(float)>>>(
        w, W1r, b1r, W2r, b2r, W1v, b1v, W2v, b2v);

    dim3 g2(R_TOTAL/32, 8);
    k2_layer3<<<g2, 128, K2_SMEM_BYTES>>>(
        data, W3r, b3r, W3v, b3v);

    k3_final<<<R_TOTAL/256, 256>>>(out);
}

// round 8
// speedup vs baseline: 3.8672x; 1.0162x over previous
#include <cuda_runtime.h>
#include <cuda_bf16.h>

#define R_TOTAL 65536   // T*B = 2048*32
#define XDIM    1024

// ---- scratch (static device arrays; no allocation) ----
__device__ float g_h2[(size_t)R_TOTAL * 128];   // [row][mlp(2)][64]   32 MB
__device__ float g_part[8][R_TOTAL];            // per-colblock partial row sums (log2-domain)

__device__ __forceinline__ float ex2f(float x){ float r; asm("ex2.approx.f32 %0, %1;" : "=f"(r) : "f"(x)); return r; }
__device__ __forceinline__ float lg2f(float x){ float r; asm("lg2.approx.f32 %0, %1;" : "=f"(r) : "f"(x)); return r; }

__device__ __forceinline__ float tanh_fast(float x){
    float xc = fminf(fmaxf(x, -9.0f), 9.0f);
    float e  = ex2f(xc * 2.885390081777927f);   // e^{2x}
    return __fdividef(e - 1.0f, e + 1.0f);
}

// ---- packed f32x2 helpers ----
typedef unsigned long long ull;
__device__ __forceinline__ void ffma2(ull &d, ull a, ull b){
    asm("fma.rn.f32x2 %0, %1, %2, %0;" : "+l"(d) : "l"(a), "l"(b));
}
__device__ __forceinline__ ull mul2(ull a, ull b){
    ull d; asm("mul.rn.f32x2 %0, %1, %2;" : "=l"(d) : "l"(a), "l"(b)); return d;
}
__device__ __forceinline__ ull add2(ull a, ull b){
    ull d; asm("add.rn.f32x2 %0, %1, %2;" : "=l"(d) : "l"(a), "l"(b)); return d;
}
__device__ __forceinline__ ull pk2(float lo, float hi){
    ull d; asm("mov.b64 %0, {%1, %2};" : "=l"(d) : "f"(lo), "f"(hi)); return d;
}
__device__ __forceinline__ void upk2(float &lo, float &hi, ull u){
    asm("mov.b64 {%0, %1}, %2;" : "=f"(lo), "=f"(hi) : "l"(u));
}
__device__ __forceinline__ ull dup2(float f){
    ull d; asm("mov.b64 %0, {%1, %1};" : "=l"(d) : "f"(f)); return d;
}
__device__ __forceinline__ ull pack_dup(float f){
    unsigned int b = __float_as_uint(f);
    return ((ull)b << 32) | (ull)b;
}
__device__ __forceinline__ ull pack2i(float f0, float f1){
    return ((ull)__float_as_uint(f1) << 32) | (ull)__float_as_uint(f0);
}

// ===========================================================================
// K1: layers 1+2 for both MLPs. 64 rows per block, 256 threads.
// Layer 2 uses f32x2 with ROW-pair packing via transposed h1 (h1t[m][k][r]).
// smem: xsh[64*32] | h1t[2*256*68] | w2sh[2*64*64]  = 176 KB
// ===========================================================================
#define K1_XSH   0
#define K1_H1T   (64*32)
#define K1_W2SH  (K1_H1T + 2*256*68)
#define K1_SMEM_FLOATS (K1_W2SH + 2*64*64)

__global__ void __launch_bounds__(256, 1) k1_mlp12(
    const float* __restrict__ w,
    const float* __restrict__ W1r, const float* __restrict__ b1r,
    const float* __restrict__ W2r, const float* __restrict__ b2r,
    const float* __restrict__ W1v, const float* __restrict__ b1v,
    const float* __restrict__ W2v, const float* __restrict__ b2v)
{
    extern __shared__ float sm[];
    float* xsh  = sm + K1_XSH;
    float* h1t  = sm + K1_H1T;     // [m][k][r] stride 68
    float* w2sh = sm + K1_W2SH;

    const int tid  = threadIdx.x;
    const int row0 = blockIdx.x * 64;

    {
        const float4* src = (const float4*)(w + (size_t)row0 * 32);
        float4* dst = (float4*)xsh;
        for (int i = tid; i < 64*32/4; i += 256) dst[i] = src[i];
    }

    // ---- layer 1: thread owns output col c (= layer-2 k index) ----
    const int c = tid;
    float w1a[16], w1b[16];
    #pragma unroll
    for (int k = 0; k < 16; k++){ w1a[k] = W1r[k*256 + c]; w1b[k] = W1v[k*256 + c]; }
    const float ba = b1r[c], bb = b1v[c];
    __syncthreads();

    #pragma unroll 2
    for (int r2 = 0; r2 < 64; r2 += 2){
        float h0p[2], h1p[2];
        #pragma unroll
        for (int u = 0; u < 2; u++){
            const int r = r2 + u;
            float xr[32];
            #pragma unroll
            for (int q = 0; q < 8; q++) *(float4*)&xr[q*4] = *(float4*)&xsh[r*32 + q*4];
            float a0 = ba, a1 = bb;
            #pragma unroll
            for (int k = 0; k < 8; k++){
                a0 = fmaf(xr[k],      w1a[k],     a0);
                a0 = fmaf(xr[k + 16], w1a[k + 8], a0);
                a1 = fmaf(xr[k + 8],  w1b[k],     a1);
                a1 = fmaf(xr[k + 24], w1b[k + 8], a1);
            }
            h0p[u] = tanh_fast(a0);
            h1p[u] = tanh_fast(a1);
        }
        // transposed store: rows adjacent => natural f32x2 pairs later
        *(ull*)&h1t[(0*256 + c)*68 + r2] = pack2i(h0p[0], h0p[1]);
        *(ull*)&h1t[(1*256 + c)*68 + r2] = pack2i(h1p[0], h1p[1]);
    }

    // ---- layer 2: thread tile = 4 rows (2 packed pairs) x 4 cols x 2 mlps ----
    const int ci = tid & 15, rg = tid >> 4;
    const int c0 = ci * 4,  r0 = rg * 4;

    ull acc[2][2][4];   // [mlp][rowpair][col], bias dup'd across the pair
    {
        float4 br = *(const float4*)&b2r[c0];
        float4 bv = *(const float4*)&b2v[c0];
        #pragma unroll
        for (int rp = 0; rp < 2; rp++){
            acc[0][rp][0] = pack_dup(br.x); acc[0][rp][1] = pack_dup(br.y);
            acc[0][rp][2] = pack_dup(br.z); acc[0][rp][3] = pack_dup(br.w);
            acc[1][rp][0] = pack_dup(bv.x); acc[1][rp][1] = pack_dup(bv.y);
            acc[1][rp][2] = pack_dup(bv.z); acc[1][rp][3] = pack_dup(bv.w);
        }
    }

    for (int kc = 0; kc < 4; kc++){      // K = 256 in chunks of 64
        __syncthreads();
        for (int q = tid; q < 2048; q += 256){   // stage W2 chunk [2][64][64] (float4)
            int m   = q >> 10;
            int rem = q & 1023;
            int kk  = rem >> 4;
            int cq  = rem & 15;
            const float* W2m = m ? W2v : W2r;
            *(float4*)&w2sh[(m*64 + kk)*64 + cq*4] =
                *(const float4*)&W2m[(kc*64 + kk)*64 + cq*4];
        }
        __syncthreads();
        #pragma unroll 4
        for (int kk = 0; kk < 64; kk++){
            const int k = kc*64 + kk;
            float4 wr = *(float4*)&w2sh[(0*64 + kk)*64 + c0];
            float4 wv = *(float4*)&w2sh[(1*64 + kk)*64 + c0];
            // rows r0..r0+3 of h1 at this k, both mlps (broadcast LDS.128)
            ulonglong2 hA = *(const ulonglong2*)&h1t[(0*256 + k)*68 + r0];
            ulonglong2 hB = *(const ulonglong2*)&h1t[(1*256 + k)*68 + r0];
            ull wd;
            wd = dup2(wr.x); ffma2(acc[0][0][0], hA.x, wd); ffma2(acc[0][1][0], hA.y, wd);
            wd = dup2(wr.y); ffma2(acc[0][0][1], hA.x, wd); ffma2(acc[0][1][1], hA.y, wd);
            wd = dup2(wr.z); ffma2(acc[0][0][2], hA.x, wd); ffma2(acc[0][1][2], hA.y, wd);
            wd = dup2(wr.w); ffma2(acc[0][0][3], hA.x, wd); ffma2(acc[0][1][3], hA.y, wd);
            wd = dup2(wv.x); ffma2(acc[1][0][0], hB.x, wd); ffma2(acc[1][1][0], hB.y, wd);
            wd = dup2(wv.y); ffma2(acc[1][0][1], hB.x, wd); ffma2(acc[1][1][1], hB.y, wd);
            wd = dup2(wv.z); ffma2(acc[1][0][2], hB.x, wd); ffma2(acc[1][1][2], hB.y, wd);
            wd = dup2(wv.w); ffma2(acc[1][0][3], hB.x, wd); ffma2(acc[1][1][3], hB.y, wd);
        }
    }

    // tanh + store h2: rows r0 + rp*2 + half
    #pragma unroll
    for (int m = 0; m < 2; m++){
        #pragma unroll
        for (int rp = 0; rp < 2; rp++){
            float lo0, hi0, lo1, hi1, lo2, hi2, lo3, hi3;
            upk2(lo0, hi0, acc[m][rp][0]);
            upk2(lo1, hi1, acc[m][rp][1]);
            upk2(lo2, hi2, acc[m][rp][2]);
            upk2(lo3, hi3, acc[m][rp][3]);
            float4 oLo, oHi;
            oLo.x = tanh_fast(lo0); oLo.y = tanh_fast(lo1);
            oLo.z = tanh_fast(lo2); oLo.w = tanh_fast(lo3);
            oHi.x = tanh_fast(hi0); oHi.y = tanh_fast(hi1);
            oHi.z = tanh_fast(hi2); oHi.w = tanh_fast(hi3);
            const int rowLo = row0 + r0 + rp*2;
            *(float4*)&g_h2[((size_t)rowLo*2 + m)*64 + c0]       = oLo;
            *(float4*)&g_h2[((size_t)(rowLo+1)*2 + m)*64 + c0]   = oHi;
        }
    }
}

// ===========================================================================
// K2: layer 3 + decode + prime-factored Z + reduction. (unchanged from R7)
// ===========================================================================
#define K2_OFF_W3   (32*128*8)                 // 32768
#define K2_OFF_DATA (K2_OFF_W3 + 2*64*128*4)   // 98304
#define K2_OFF_LUT  (K2_OFF_DATA + 32*128*4)   // 114688
#define K2_SMEM_BYTES (K2_OFF_LUT + 64)        // 114752

__global__ void __launch_bounds__(128, 2) k2_layer3(
    const float* __restrict__ data,
    const float* __restrict__ W3r, const float* __restrict__ b3r,
    const float* __restrict__ W3v, const float* __restrict__ b3v)
{
    extern __shared__ __align__(16) char smraw[];
    ull*   h2p  = (ull*)smraw;                       // 4096 ull
    float* w3sh = (float*)(smraw + K2_OFF_W3);       // 16384 floats
    float* dsh  = (float*)(smraw + K2_OFF_DATA);     // 4096 floats
    float* lut  = (float*)(smraw + K2_OFF_LUT);      // 10 floats: ln(d!)

    const int tid  = threadIdx.x;
    const int row0 = blockIdx.x * 32;
    const int cb   = blockIdx.y;
    const int wid  = tid >> 5;
    const int lane = tid & 31;

    {
        unsigned int dsh_base = (unsigned int)__cvta_generic_to_shared(dsh);
        #pragma unroll
        for (int i = 0; i < 8; i++){
            int q  = tid + i*128;
            int rr = q >> 5, cf = q & 31;
            const float* src = data + (size_t)(row0 + rr)*1024 + cb*128 + cf*4;
            asm volatile("cp.async.cg.shared.global [%0], [%1], 16;"
                         :: "r"(dsh_base + q*16), "l"(src));
        }
        asm volatile("cp.async.commit_group;");
    }

    if (tid < 10){
        const float LGF[10] = {
            0.0f, 0.0f, 0.6931471805599453f, 1.791759469228055f, 3.1780538303479458f,
            4.787491742782046f, 6.579251212010101f, 8.525161361065415f,
            10.604602902745251f, 12.801827480081469f };
        lut[tid] = LGF[tid];
    }

    for (int q = tid; q < 4096; q += 128){
        int rr  = q >> 7;
        int rem = q & 127;
        h2p[rr*128 + rem] = pack_dup(g_h2[(size_t)(row0 + rr)*128 + rem]);
    }
    {
        float4* dst = (float4*)w3sh;
        const float4* s0 = (const float4*)W3r;
        const float4* s1 = (const float4*)W3v;
        for (int q = tid; q < 4096; q += 128){
            int m  = q >> 11;
            int kk = (q >> 5) & 63;
            int cf = q & 31;
            dst[q] = (m ? s1 : s0)[kk*256 + cb*32 + cf];
        }
    }
    __syncthreads();

    ull acc[2][8][2];
    {
        const float4* br4 = (const float4*)b3r;
        const float4* bv4 = (const float4*)b3v;
        float4 br = br4[cb*32 + lane];
        float4 bv = bv4[cb*32 + lane];
        #pragma unroll
        for (int rr = 0; rr < 8; rr++){
            acc[0][rr][0] = pack2i(br.x, br.y);
            acc[0][rr][1] = pack2i(br.z, br.w);
            acc[1][rr][0] = pack2i(bv.x, bv.y);
            acc[1][rr][1] = pack2i(bv.z, bv.w);
        }
    }

    const ulonglong2* w3u = (const ulonglong2*)w3sh;
    const ull* h2row = h2p + wid*8*128;
    #pragma unroll 4
    for (int k = 0; k < 64; k += 2){
        ulonglong2 wr0 = w3u[(size_t)k*32 + lane];
        ulonglong2 wr1 = w3u[(size_t)(k+1)*32 + lane];
        ulonglong2 wv0 = w3u[(size_t)(64 + k)*32 + lane];
        ulonglong2 wv1 = w3u[(size_t)(64 + k + 1)*32 + lane];
        #pragma unroll
        for (int rr = 0; rr < 8; rr++){
            ulonglong2 h0p = *(const ulonglong2*)&h2row[rr*128 + k];
            ulonglong2 h1p = *(const ulonglong2*)&h2row[rr*128 + 64 + k];
            ffma2(acc[0][rr][0], h0p.x, wr0.x);
            ffma2(acc[0][rr][1], h0p.x, wr0.y);
            ffma2(acc[0][rr][0], h0p.y, wr1.x);
            ffma2(acc[0][rr][1], h0p.y, wr1.y);
            ffma2(acc[1][rr][0], h1p.x, wv0.x);
            ffma2(acc[1][rr][1], h1p.x, wv0.y);
            ffma2(acc[1][rr][0], h1p.y, wv1.x);
            ffma2(acc[1][rr][1], h1p.y, wv1.y);
        }
    }

    asm volatile("cp.async.wait_group 0;");
    __syncthreads();

    const float LOG2E = 1.4426950408889634f;
    const float C_NLG2LN2 = 0.5287663729448977f;   // -log2(ln 2)
    const ull   ONE2 = 0x3F8000003F800000ULL;
    const float LNP3  = 1.0986122886681098f;
    const float LNP5  = 1.6094379124341003f;
    const float LNP7  = 1.9459101090932196f;
    const float LNP11 = 2.3978952727983707f;
    const float LNP13 = 2.5649493574615367f;
    const float LNP17 = 2.833213344056216f;
    const float LNP19 = 2.9444389791664403f;
    const float LN2c  = 0.6931471805599453f;

    float srow[8];
    #pragma unroll
    for (int rr = 0; rr < 8; rr++) srow[rr] = 0.0f;

    #pragma unroll
    for (int rr = 0; rr < 8; rr++){
        const int rl = wid*8 + rr;
        float4 d4 = *(const float4*)&dsh[rl*128 + lane*4];
        float dvp[2][2] = {{d4.x, d4.y}, {d4.z, d4.w}};

        #pragma unroll
        for (int p = 0; p < 2; p++){
            float ya0, ya1, yb0, yb1;
            upk2(ya0, ya1, acc[0][rr][p]);
            upk2(yb0, yb1, acc[1][rr][p]);

            float lr2h[2], sbh[2], rateh[2];
            #pragma unroll
            for (int h = 0; h < 2; h++){
                float ya = h ? ya1 : ya0;
                float yb = h ? yb1 : yb0;
                float ta  = ya * LOG2E;
                float spa = fmaxf(ta, 0.0f) + lg2f(1.0f + ex2f(-fabsf(ta)));
                lr2h[h]   = C_NLG2LN2 - lg2f(spa);
                float tb  = yb * LOG2E;
                sbh[h]    = fmaxf(tb, 0.0f) + lg2f(1.0f + ex2f(-fabsf(tb)));
                rateh[h]  = ex2f(lr2h[h]);
            }

            ull A2  = pk2(ex2f(-sbh[0]*LN2c),  ex2f(-sbh[1]*LN2c));
            ull A3  = pk2(ex2f(-sbh[0]*LNP3),  ex2f(-sbh[1]*LNP3));
            ull A5  = pk2(ex2f(-sbh[0]*LNP5),  ex2f(-sbh[1]*LNP5));
            ull A7  = pk2(ex2f(-sbh[0]*LNP7),  ex2f(-sbh[1]*LNP7));
            ull A11 = pk2(ex2f(-sbh[0]*LNP11), ex2f(-sbh[1]*LNP11));
            ull A13 = pk2(ex2f(-sbh[0]*LNP13), ex2f(-sbh[1]*LNP13));
            ull A17 = pk2(ex2f(-sbh[0]*LNP17), ex2f(-sbh[1]*LNP17));
            ull A19 = pk2(ex2f(-sbh[0]*LNP19), ex2f(-sbh[1]*LNP19));

            ull R = pk2(rateh[0], rateh[1]);

            ull B2  = mul2(R, A2);
            ull B3  = mul2(R, A3);
            ull B5  = mul2(R, A5);
            ull B7  = mul2(R, A7);
            ull B11 = mul2(R, A11);
            ull B13 = mul2(R, A13);
            ull B17 = mul2(R, A17);
            ull B19 = mul2(R, A19);
            ull B4  = mul2(B2, A2);
            ull B6  = mul2(B2, A3);
            ull B8  = mul2(B4, A2);
            ull B9  = mul2(B3, A3);
            ull B10 = mul2(B2, A5);
            ull B12 = mul2(B4, A3);
            ull B14 = mul2(B2, A7);
            ull B15 = mul2(B3, A5);
            ull B16 = mul2(B8, A2);
            ull B18 = mul2(B9, A2);

            ull t = R;
            ull Z = add2(ONE2, t);
            t = mul2(t, B2);  Z = add2(Z, t);
            t = mul2(t, B3);  Z = add2(Z, t);
            t = mul2(t, B4);  Z = add2(Z, t);
            t = mul2(t, B5);  Z = add2(Z, t);
            t = mul2(t, B6);  Z = add2(Z, t);
            t = mul2(t, B7);  Z = add2(Z, t);
            t = mul2(t, B8);  Z = add2(Z, t);
            t = mul2(t, B9);  Z = add2(Z, t);
            t = mul2(t, B10); Z = add2(Z, t);
            t = mul2(t, B11); Z = add2(Z, t);
            t = mul2(t, B12); Z = add2(Z, t);
            t = mul2(t, B13); Z = add2(Z, t);
            t = mul2(t, B14); Z = add2(Z, t);
            t = mul2(t, B15); Z = add2(Z, t);
            t = mul2(t, B16); Z = add2(Z, t);
            t = mul2(t, B17); Z = add2(Z, t);
            t = mul2(t, B18); Z = add2(Z, t);
            t = mul2(t, B19); Z = add2(Z, t);

            float Z0, Z1;
            upk2(Z0, Z1, Z);
            #pragma unroll
            for (int h = 0; h < 2; h++){
                float Zh  = h ? Z1 : Z0;
                float d   = dvp[p][h];
                float lgfd = lut[(int)d];
                float x = fmaf(-d, lr2h[h], lg2f(Zh));
                srow[rr] += fmaf(sbh[h], lgfd, x);
            }
        }
    }

    #pragma unroll
    for (int rr = 0; rr < 8; rr++){
        float s = srow[rr];
        s += __shfl_xor_sync(0xffffffffu, s, 1);
        s += __shfl_xor_sync(0xffffffffu, s, 2);
        s += __shfl_xor_sync(0xffffffffu, s, 4);
        s += __shfl_xor_sync(0xffffffffu, s, 8);
        s += __shfl_xor_sync(0xffffffffu, s, 16);
        srow[rr] = s;
    }
    if (lane == 0){
        #pragma unroll
        for (int rr = 0; rr < 8; rr++)
            g_part[cb][row0 + wid*8 + rr] = srow[rr];
    }
}

// ===========================================================================
// K3: finalize — sum colblock partials, scale by LN2/1024
// ===========================================================================
__global__ void k3_final(float* __restrict__ out)
{
    int row = blockIdx.x * 256 + threadIdx.x;
    float s = 0.0f;
    #pragma unroll
    for (int cb = 0; cb < 8; cb++) s += g_part[cb][row];
    out[row] = s * 6.7690154351557146e-4f;   // ln2 / 1024
}

// ===========================================================================
extern "C" void kernel_launch(void* const* d_in, const int* in_sizes, int n_in,
                              void* d_out, int out_size)
{
    const float* w    = (const float*)d_in[0];
    const float* data = (const float*)d_in[1];
    const float* W1r  = (const float*)d_in[2];
    const float* b1r  = (const float*)d_in[3];
    const float* W2r  = (const float*)d_in[4];
    const float* b2r  = (const float*)d_in[5];
    const float* W3r  = (const float*)d_in[6];
    const float* b3r  = (const float*)d_in[7];
    const float* W1v  = (const float*)d_in[8];
    const float* b1v  = (const float*)d_in[9];
    const float* W2v  = (const float*)d_in[10];
    const float* b2v  = (const float*)d_in[11];
    const float* W3v  = (const float*)d_in[12];
    const float* b3v  = (const float*)d_in[13];
    float* out = (float*)d_out;

    static bool attr_set = false;
    if (!attr_set){
        cudaFuncSetAttribute(k1_mlp12, cudaFuncAttributeMaxDynamicSharedMemorySize,
                             K1_SMEM_FLOATS * (int)sizeof(float));
        cudaFuncSetAttribute(k2_layer3, cudaFuncAttributeMaxDynamicSharedMemorySize,
                             K2_SMEM_BYTES);
        attr_set = true;
    }

    k1_mlp12<<<R_TOTAL/64, 256, K1_SMEM_FLOATS * sizeof(float)>>>(
        w, W1r, b1r, W2r, b2r, W1v, b1v, W2v, b2v);

    dim3 g2(R_TOTAL/32, 8);
    k2_layer3<<<g2, 128, K2_SMEM_BYTES>>>(
        data, W3r, b3r, W3v, b3v);

    k3_final<<<R_TOTAL/256, 256>>>(out);
}